// round 12
// baseline (speedup 1.0000x reference)
#include <cuda_runtime.h>
#include <cuda_fp16.h>
#include <cstdint>

typedef unsigned long long ull;

// Precomputed g = feats @ w_in[0:64,:] + b_in  (N x 64), stored fp16
__device__ __half g_buf[100000 * 64];
// Packed fp16 weights: [w1, w2], each 64x64 fp16 = 2048 u32
__device__ uint32_t w_pack[2][2048];
// float4-padded points; apts4.w carries the label as float
__device__ float4 pcd4[100000];
__device__ float4 apts4[100000];

// ---------------------------------------------------------------------------
// helpers
// ---------------------------------------------------------------------------
__device__ __forceinline__ ull pack2(float lo, float hi) {
    ull r; asm("mov.b64 %0, {%1, %2};" : "=l"(r) : "f"(lo), "f"(hi)); return r;
}
__device__ __forceinline__ ull bcast2(float v) { return pack2(v, v); }
__device__ __forceinline__ ull ffma2(ull a, ull b, ull c) {
    ull d; asm("fma.rn.f32x2 %0, %1, %2, %3;" : "=l"(d) : "l"(a), "l"(b), "l"(c)); return d;
}
__device__ __forceinline__ void unpack2(ull v, float& lo, float& hi) {
    asm("mov.b64 {%0, %1}, %2;" : "=f"(lo), "=f"(hi) : "l"(v));
}
__device__ __forceinline__ uint32_t smem_u32(const void* p) {
    uint32_t a;
    asm("{ .reg .u64 t; cvta.to.shared.u64 t, %1; cvt.u32.u64 %0, t; }" : "=r"(a) : "l"(p));
    return a;
}
__device__ __forceinline__ uint32_t pack_f16x2(float lo, float hi) {
    __half2 h = __floats2half2_rn(lo, hi);      // lo -> low half
    return *reinterpret_cast<uint32_t*>(&h);
}
__device__ __forceinline__ __half2 u2h2(uint32_t v) {
    return *reinterpret_cast<__half2*>(&v);
}
__device__ __forceinline__ uint32_t h2u2(__half2 v) {
    return *reinterpret_cast<uint32_t*>(&v);
}
__device__ __forceinline__ void ldsm_x4(uint32_t* r, uint32_t addr) {
    asm volatile("ldmatrix.sync.aligned.m8n8.x4.shared.b16 {%0,%1,%2,%3}, [%4];"
                 : "=r"(r[0]), "=r"(r[1]), "=r"(r[2]), "=r"(r[3]) : "r"(addr));
}
__device__ __forceinline__ void ldsm_x4_t(uint32_t* r, uint32_t addr) {
    asm volatile("ldmatrix.sync.aligned.m8n8.x4.trans.shared.b16 {%0,%1,%2,%3}, [%4];"
                 : "=r"(r[0]), "=r"(r[1]), "=r"(r[2]), "=r"(r[3]) : "r"(addr));
}
__device__ __forceinline__ void mma16816(float* c, const uint32_t* a, const uint32_t* b) {
    asm volatile(
        "mma.sync.aligned.m16n8k16.row.col.f32.f16.f16.f32 "
        "{%0,%1,%2,%3}, {%4,%5,%6,%7}, {%8,%9}, {%0,%1,%2,%3};"
        : "+f"(c[0]), "+f"(c[1]), "+f"(c[2]), "+f"(c[3])
        : "r"(a[0]), "r"(a[1]), "r"(a[2]), "r"(a[3]), "r"(b[0]), "r"(b[1]));
}
__device__ __forceinline__ void cp_async16(uint32_t smem_addr, const void* gptr) {
    asm volatile("cp.async.cg.shared.global [%0], [%1], 16;"
                 :: "r"(smem_addr), "l"(gptr) : "memory");
}

// ---------------------------------------------------------------------------
// Kernel 1 (fused prologue):
//   blocks [0, G):        g[n,:] = fp16(feats[n,:] @ w_in[0:64,:] + b_in)
//   blocks [G, G+16):     fp16 conversion of w1, w2
//   blocks [G+16, end):   pad pcd/apts into float4 (label -> apts4.w)
// ---------------------------------------------------------------------------
__global__ void __launch_bounds__(128) precompute_kernel(
    const float* __restrict__ feats, const float* __restrict__ w_in,
    const float* __restrict__ b_in, int n_pts,
    const float* __restrict__ w1g, const float* __restrict__ w2g,
    const float* __restrict__ pcd, int nPcd,
    const float* __restrict__ apts, const int* __restrict__ labels, int nApts,
    int gBlocks)
{
    if (blockIdx.x >= (unsigned)(gBlocks + 16)) {
        int i = (blockIdx.x - gBlocks - 16) * 128 + threadIdx.x;
        if (i < nPcd)
            pcd4[i] = make_float4(pcd[3 * i], pcd[3 * i + 1], pcd[3 * i + 2], 0.0f);
        if (i < nApts)
            apts4[i] = make_float4(apts[3 * i], apts[3 * i + 1], apts[3 * i + 2],
                                   (float)labels[i]);
        return;
    }
    if (blockIdx.x >= (unsigned)gBlocks) {
        int idx = (blockIdx.x - gBlocks) * 128 + threadIdx.x;  // 0..2047
        w_pack[0][idx] = pack_f16x2(w1g[2 * idx], w1g[2 * idx + 1]);
        w_pack[1][idx] = pack_f16x2(w2g[2 * idx], w2g[2 * idx + 1]);
        return;
    }

    __shared__ __align__(16) ull s_w[2048];
    for (int idx = threadIdx.x; idx < 2048; idx += 128)
        s_w[idx] = ((const ull*)w_in)[idx];
    __syncthreads();

    int n = blockIdx.x * 128 + threadIdx.x;
    if (n >= n_pts) return;

    float act[64];
    const float4* fp = (const float4*)(feats + (size_t)n * 64);
#pragma unroll
    for (int i = 0; i < 16; i++) {
        float4 v = fp[i];
        act[4 * i] = v.x; act[4 * i + 1] = v.y; act[4 * i + 2] = v.z; act[4 * i + 3] = v.w;
    }
    ull acc[32];
    const ull* bp = (const ull*)b_in;
#pragma unroll
    for (int j = 0; j < 32; j++) acc[j] = bp[j];
#pragma unroll
    for (int i = 0; i < 64; i++) {
        ull a2 = bcast2(act[i]);
#pragma unroll
        for (int j = 0; j < 32; j += 2) {
            ulonglong2 w = *reinterpret_cast<const ulonglong2*>(&s_w[i * 32 + j]);
            acc[j] = ffma2(a2, w.x, acc[j]);
            acc[j + 1] = ffma2(a2, w.y, acc[j + 1]);
        }
    }
    uint32_t h[32];
#pragma unroll
    for (int j = 0; j < 32; j++) {
        float f0, f1; unpack2(acc[j], f0, f1);
        h[j] = pack_f16x2(f0, f1);
    }
    uint4* gp = (uint4*)(g_buf + (size_t)n * 64);
#pragma unroll
    for (int q = 0; q < 8; q++)
        gp[q] = make_uint4(h[4 * q], h[4 * q + 1], h[4 * q + 2], h[4 * q + 3]);
}

// ---------------------------------------------------------------------------
// Kernel 2: persistent mma.sync edge MLP with cp.async-pipelined g gather.
// 128 edges/tile, 4 warps, 32 edges/warp. Double-buffered raw-g SMEM staging.
// SMEM (bytes):
//   [0)      2 weight tiles [64][72 fp16] (144B stride): w1, w2       18432
//   [18432)  A tile [128][72] fp16 (144B stride)                       18432
//   [36864)  g staging, 2 bufs x [128][144B]                           36864
//   [73728)  w3 (3x64 f32), [74496) w_out, [75008) b1, [75264) b2, [75520) b_out
// ---------------------------------------------------------------------------
#define SM_W     0
#define SM_A     18432
#define SM_GR    36864
#define SM_W3    73728
#define SM_WOUT  74496
#define SM_B1    75008
#define SM_B2    75264
#define SM_BOUT  75520
#define SM_TOTAL 75776

__global__ void __launch_bounds__(128, 3) edge_mma_kernel(
    const int* __restrict__ row,
    const int* __restrict__ col,
    const float* __restrict__ w_in,
    const float* __restrict__ b1g,
    const float* __restrict__ b2g,
    const float* __restrict__ w_outg, const float* __restrict__ b_outg,
    float* __restrict__ out,
    int nE, int nTiles, int write_labels)
{
    extern __shared__ __align__(16) char smem[];
    const int tid = threadIdx.x;
    const int lane = tid & 31;
    const int warp = tid >> 5;
    const uint32_t FULL = 0xFFFFFFFFu;

    // ---- stage weights into SMEM (144B row stride, conflict-free ldsm) ----
#pragma unroll
    for (int m = 0; m < 2; m++) {
        for (int idx = tid; idx < 2048; idx += 128) {
            int rk = idx >> 5, cc = idx & 31;
            *(uint32_t*)(smem + SM_W + m * 9216 + rk * 144 + cc * 4) = w_pack[m][idx];
        }
    }
    float* s_w3 = (float*)(smem + SM_W3);
    float* s_wout = (float*)(smem + SM_WOUT);
    float* s_b1 = (float*)(smem + SM_B1);
    float* s_b2 = (float*)(smem + SM_B2);
    float* s_bout = (float*)(smem + SM_BOUT);
    for (int idx = tid; idx < 192; idx += 128) s_w3[idx] = w_in[64 * 64 + idx];
    if (tid < 128) s_wout[tid] = w_outg[tid];
    if (tid < 64) { s_b1[tid] = b1g[tid]; s_b2[tid] = b2g[tid]; }
    if (tid < 2) s_bout[tid] = b_outg[tid];
    __syncthreads();

    const uint32_t sbase = smem_u32(smem);
    const uint32_t sA = sbase + SM_A;
    const uint32_t sGR = sbase + SM_GR;

    const int a_row = (lane & 7) + ((lane >> 3) & 1) * 8;      // 0..15
    const int a_c8 = ((lane >> 4) & 1) * 8;                     // 0 / +8 cols
    const int b_row = (lane & 7) + ((lane >> 3) & 3) * 8;       // 0..31

    // per-lane cooperative-gather mapping + w3 column slice as half2 (constant)
    const int esub = lane >> 3;          // which of 4 edges this lane serves
    const int part = lane & 7;           // which 16B chunk of the row
    __half2 w3h[3][4];
#pragma unroll
    for (int rr = 0; rr < 3; rr++)
#pragma unroll
        for (int p = 0; p < 4; p++)
            w3h[rr][p] = __floats2half2_rn(s_w3[rr * 64 + part * 8 + 2 * p],
                                           s_w3[rr * 64 + part * 8 + 2 * p + 1]);
    const __half2 hzero = __floats2half2_rn(0.0f, 0.0f);
    // this lane's staging slot base (row = warp*32 + eg, chunk = part)
    const uint32_t myGR = sGR + (uint32_t)(warp * 32) * 144 + part * 16;

    // ---- prologue: indices + pos for first tile; cp.async its g rows ----
    int r = 0, c = 0;
    if (blockIdx.x < nTiles) {
        int e0 = blockIdx.x * 128 + tid;
        int ee = e0 < nE ? e0 : nE - 1;
        r = row[ee]; c = col[ee];
    }
    int buf = 0;
    {
#pragma unroll
        for (int i = 0; i < 8; i++) {
            const int eg = 4 * i + esub;
            const int cg = __shfl_sync(FULL, c, eg);
            cp_async16(myGR + 0 * 18432 + (uint32_t)eg * 144,
                       g_buf + (size_t)cg * 64 + part * 8);
        }
        asm volatile("cp.async.commit_group;" ::: "memory");
    }
    float4 ap = apts4[r];
    float4 pc = pcd4[c];

    for (int tile = blockIdx.x; tile < nTiles; tile += gridDim.x) {
        const int e = tile * 128 + tid;
        const bool valid = e < nE;

        // ---- next tile's indices + issue its g-row copies into buf^1 ----
        int rn = r, cn = c;
        {
            int tn = tile + gridDim.x;
            if (tn < nTiles) {
                int en = tn * 128 + tid;
                int een = en < nE ? en : nE - 1;
                rn = row[een]; cn = col[een];
#pragma unroll
                for (int i = 0; i < 8; i++) {
                    const int eg = 4 * i + esub;
                    const int cg = __shfl_sync(FULL, cn, eg);
                    cp_async16(myGR + (buf ^ 1) * 18432 + (uint32_t)eg * 144,
                               g_buf + (size_t)cg * 64 + part * 8);
                }
            }
            asm volatile("cp.async.commit_group;" ::: "memory");
        }

        const uint32_t h00 = pack_f16x2(ap.x - pc.x, ap.x - pc.x);
        const uint32_t h11 = pack_f16x2(ap.y - pc.y, ap.y - pc.y);
        const uint32_t h22 = pack_f16x2(ap.z - pc.z, ap.z - pc.z);
        const float lab = ap.w;

        // wait for THIS tile's g rows (1 group may remain in flight)
        asm volatile("cp.async.wait_group 1;" ::: "memory");
        __syncwarp();

        // ---- stage A (from SMEM staging, half2): 8 lanes per edge row ----
#pragma unroll
        for (int i = 0; i < 8; i++) {
            const int eg = 4 * i + esub;                       // edge-in-warp
            const __half2 q0 = u2h2(__shfl_sync(FULL, h00, eg));
            const __half2 q1 = u2h2(__shfl_sync(FULL, h11, eg));
            const __half2 q2 = u2h2(__shfl_sync(FULL, h22, eg));
            uint32_t w[4];
            asm volatile("ld.shared.v4.b32 {%0,%1,%2,%3}, [%4];"
                         : "=r"(w[0]), "=r"(w[1]), "=r"(w[2]), "=r"(w[3])
                         : "r"(myGR + buf * 18432 + (uint32_t)eg * 144));
            uint32_t h4[4];
#pragma unroll
            for (int p = 0; p < 4; p++) {
                __half2 hv = u2h2(w[p]);
                hv = __hfma2(q0, w3h[0][p], hv);
                hv = __hfma2(q1, w3h[1][p], hv);
                hv = __hfma2(q2, w3h[2][p], hv);
                hv = __hmax2(hv, hzero);
                h4[p] = h2u2(hv);
            }
            asm volatile("st.shared.v4.b32 [%0], {%1,%2,%3,%4};" ::
                         "r"(sA + (uint32_t)(warp * 32 + eg) * 144 + part * 16),
                         "r"(h4[0]), "r"(h4[1]), "r"(h4[2]), "r"(h4[3]));
        }
        __syncwarp();

        // ---- load A fragments (layer 1) ----
        uint32_t A[2][4][4];
#pragma unroll
        for (int mt = 0; mt < 2; mt++) {
            const int rowm = warp * 32 + mt * 16 + a_row;
#pragma unroll
            for (int kt = 0; kt < 4; kt++)
                ldsm_x4(A[mt][kt], sA + (uint32_t)rowm * 144 + (kt * 16 + a_c8) * 2);
        }

        float C[2][8][4];

        // ===================== two hidden layers =====================
#pragma unroll
        for (int L = 0; L < 2; L++) {
#pragma unroll
            for (int mt = 0; mt < 2; mt++)
#pragma unroll
                for (int nt = 0; nt < 8; nt++)
#pragma unroll
                    for (int i = 0; i < 4; i++) C[mt][nt][i] = 0.0f;

            const uint32_t wbase = sbase + SM_W + L * 9216;
#pragma unroll
            for (int kg = 0; kg < 2; kg++) {
#pragma unroll
                for (int nt = 0; nt < 8; nt++) {
                    uint32_t B[4];
                    ldsm_x4_t(B, wbase + (uint32_t)(kg * 32 + b_row) * 144 + nt * 16);
#pragma unroll
                    for (int mt = 0; mt < 2; mt++) {
                        mma16816(C[mt][nt], A[mt][2 * kg], B);
                        mma16816(C[mt][nt], A[mt][2 * kg + 1], B + 2);
                    }
                }
            }

            if (L == 0) {
                // epilogue 1: x = relu(C + b1) -> new A fragments in registers
#pragma unroll
                for (int mt = 0; mt < 2; mt++) {
#pragma unroll
                    for (int kt = 0; kt < 4; kt++) {
#pragma unroll
                        for (int half = 0; half < 2; half++) {
                            const int nt = 2 * kt + half;
                            const int col0 = nt * 8 + (lane & 3) * 2;
                            float2 bb = *(const float2*)(s_b1 + col0);
                            A[mt][kt][2 * half + 0] =
                                pack_f16x2(fmaxf(C[mt][nt][0] + bb.x, 0.0f),
                                           fmaxf(C[mt][nt][1] + bb.y, 0.0f));
                            A[mt][kt][2 * half + 1] =
                                pack_f16x2(fmaxf(C[mt][nt][2] + bb.x, 0.0f),
                                           fmaxf(C[mt][nt][3] + bb.y, 0.0f));
                        }
                    }
                }
            }
        }

        // ---- final epilogue: logits = (C + b2) @ w_out + b_out; softmax ----
#pragma unroll
        for (int mt = 0; mt < 2; mt++) {
            float l0a = 0.0f, l1a = 0.0f, l0b = 0.0f, l1b = 0.0f;
#pragma unroll
            for (int nt = 0; nt < 8; nt++) {
                const int col0 = nt * 8 + (lane & 3) * 2;
                float2 bb = *(const float2*)(s_b2 + col0);
                float4 wo = *(const float4*)(s_wout + 2 * col0);
                float x0 = C[mt][nt][0] + bb.x;
                float x1 = C[mt][nt][1] + bb.y;
                float x2 = C[mt][nt][2] + bb.x;
                float x3 = C[mt][nt][3] + bb.y;
                l0a = fmaf(x0, wo.x, fmaf(x1, wo.z, l0a));
                l1a = fmaf(x0, wo.y, fmaf(x1, wo.w, l1a));
                l0b = fmaf(x2, wo.x, fmaf(x3, wo.z, l0b));
                l1b = fmaf(x2, wo.y, fmaf(x3, wo.w, l1b));
            }
#pragma unroll
            for (int off = 1; off <= 2; off <<= 1) {
                l0a += __shfl_xor_sync(FULL, l0a, off);
                l1a += __shfl_xor_sync(FULL, l1a, off);
                l0b += __shfl_xor_sync(FULL, l0b, off);
                l1b += __shfl_xor_sync(FULL, l1b, off);
            }
            if ((lane & 3) == 0) {
                const int e0 = tile * 128 + warp * 32 + mt * 16 + (lane >> 2);
                float la0 = l0a + s_bout[0], la1 = l1a + s_bout[1];
                float m0 = fmaxf(la0, la1);
                float ea = __expf(la0 - m0), eb = __expf(la1 - m0);
                float inv = 1.0f / (ea + eb);
                if (e0 < nE)
                    *(float2*)(out + 2 * (size_t)e0) = make_float2(ea * inv, eb * inv);

                const int e1 = e0 + 8;
                float lb0 = l0b + s_bout[0], lb1 = l1b + s_bout[1];
                float m1 = fmaxf(lb0, lb1);
                float ec = __expf(lb0 - m1), ed = __expf(lb1 - m1);
                float inv2 = 1.0f / (ec + ed);
                if (e1 < nE)
                    *(float2*)(out + 2 * (size_t)e1) = make_float2(ec * inv2, ed * inv2);
            }
        }

        if (write_labels && valid)
            out[2 * (size_t)nE + e] = lab;

        // loop-carried prefetch of next tile's pos/labels
        r = rn; c = cn;
        ap = apts4[r];
        pc = pcd4[c];
        buf ^= 1;
        __syncwarp();   // A-tile rows reused next iteration by this warp only
    }
}

// ---------------------------------------------------------------------------
extern "C" void kernel_launch(void* const* d_in, const int* in_sizes, int n_in,
                              void* d_out, int out_size)
{
    const float* pcd         = (const float*)d_in[0];
    const float* feats       = (const float*)d_in[1];
    const float* also_pts    = (const float*)d_in[2];
    const int*   also_labels = (const int*)d_in[3];
    const int*   row         = (const int*)d_in[4];
    const int*   col         = (const int*)d_in[5];
    const float* w_in        = (const float*)d_in[6];
    const float* b_in        = (const float*)d_in[7];
    const float* w1          = (const float*)d_in[8];
    const float* b1          = (const float*)d_in[9];
    const float* w2          = (const float*)d_in[10];
    const float* b2          = (const float*)d_in[11];
    const float* w_out       = (const float*)d_in[12];
    const float* b_out       = (const float*)d_in[13];

    int nPts = in_sizes[1] / 64;
    if (nPts > 100000) nPts = 100000;
    int nPcd = in_sizes[0] / 3;
    if (nPcd > 100000) nPcd = 100000;
    int nApts = in_sizes[2] / 3;
    if (nApts > 100000) nApts = 100000;
    int nE = in_sizes[4];
    int nTiles = (nE + 127) / 128;
    int write_labels = ((long long)out_size >= 3LL * nE) ? 1 : 0;

    static int attr_done = 0;
    if (!attr_done) {
        cudaFuncSetAttribute(edge_mma_kernel,
                             cudaFuncAttributeMaxDynamicSharedMemorySize, SM_TOTAL);
        attr_done = 1;
    }

    int gBlocks = (nPts + 127) / 128;
    int nmax = nPcd > nApts ? nPcd : nApts;
    int padBlocks = (nmax + 127) / 128;
    precompute_kernel<<<gBlocks + 16 + padBlocks, 128>>>(
        feats, w_in, b_in, nPts, w1, w2,
        pcd, nPcd, also_pts, also_labels, nApts, gBlocks);

    int grid = 148 * 3;
    if (grid > nTiles) grid = nTiles;
    edge_mma_kernel<<<grid, 128, SM_TOTAL>>>(row, col,
                                             w_in, b1, b2, w_out, b_out,
                                             (float*)d_out, nE, nTiles, write_labels);
}

// round 13
// speedup vs baseline: 1.2518x; 1.2518x over previous
#include <cuda_runtime.h>
#include <cuda_fp16.h>
#include <cstdint>

typedef unsigned long long ull;

// Precomputed g = feats @ w_in[0:64,:] + b_in  (N x 64), stored fp16
__device__ __half g_buf[100000 * 64];
// Packed fp16 weights: w1 only (64x64 fp16 = 2048 u32)
__device__ uint32_t w_pack[2048];
// Fused output weights: wf = w2 @ w_out (64x2 f32), bf = b2 @ w_out + b_out
__device__ float wf_buf[128];
__device__ float bf_buf[2];
// float4-padded points; apts4.w carries the label as float
__device__ float4 pcd4[100000];
__device__ float4 apts4[100000];

// ---------------------------------------------------------------------------
// helpers
// ---------------------------------------------------------------------------
__device__ __forceinline__ ull pack2(float lo, float hi) {
    ull r; asm("mov.b64 %0, {%1, %2};" : "=l"(r) : "f"(lo), "f"(hi)); return r;
}
__device__ __forceinline__ ull bcast2(float v) { return pack2(v, v); }
__device__ __forceinline__ ull ffma2(ull a, ull b, ull c) {
    ull d; asm("fma.rn.f32x2 %0, %1, %2, %3;" : "=l"(d) : "l"(a), "l"(b), "l"(c)); return d;
}
__device__ __forceinline__ void unpack2(ull v, float& lo, float& hi) {
    asm("mov.b64 {%0, %1}, %2;" : "=f"(lo), "=f"(hi) : "l"(v));
}
__device__ __forceinline__ uint32_t smem_u32(const void* p) {
    uint32_t a;
    asm("{ .reg .u64 t; cvta.to.shared.u64 t, %1; cvt.u32.u64 %0, t; }" : "=r"(a) : "l"(p));
    return a;
}
__device__ __forceinline__ uint32_t pack_f16x2(float lo, float hi) {
    __half2 h = __floats2half2_rn(lo, hi);      // lo -> low half
    return *reinterpret_cast<uint32_t*>(&h);
}
__device__ __forceinline__ __half2 u2h2(uint32_t v) {
    return *reinterpret_cast<__half2*>(&v);
}
__device__ __forceinline__ uint32_t h2u2(__half2 v) {
    return *reinterpret_cast<uint32_t*>(&v);
}
__device__ __forceinline__ void ldsm_x4(uint32_t* r, uint32_t addr) {
    asm volatile("ldmatrix.sync.aligned.m8n8.x4.shared.b16 {%0,%1,%2,%3}, [%4];"
                 : "=r"(r[0]), "=r"(r[1]), "=r"(r[2]), "=r"(r[3]) : "r"(addr));
}
__device__ __forceinline__ void ldsm_x4_t(uint32_t* r, uint32_t addr) {
    asm volatile("ldmatrix.sync.aligned.m8n8.x4.trans.shared.b16 {%0,%1,%2,%3}, [%4];"
                 : "=r"(r[0]), "=r"(r[1]), "=r"(r[2]), "=r"(r[3]) : "r"(addr));
}
__device__ __forceinline__ void mma16816(float* c, const uint32_t* a, const uint32_t* b) {
    asm volatile(
        "mma.sync.aligned.m16n8k16.row.col.f32.f16.f16.f32 "
        "{%0,%1,%2,%3}, {%4,%5,%6,%7}, {%8,%9}, {%0,%1,%2,%3};"
        : "+f"(c[0]), "+f"(c[1]), "+f"(c[2]), "+f"(c[3])
        : "r"(a[0]), "r"(a[1]), "r"(a[2]), "r"(a[3]), "r"(b[0]), "r"(b[1]));
}

// ---------------------------------------------------------------------------
// Kernel 1 (fused prologue):
//   blocks [0, G):        g[n,:] = fp16(feats[n,:] @ w_in[0:64,:] + b_in)
//   blocks [G, G+16):     fp16 conversion of w1; block G also builds wf/bf
//   blocks [G+16, end):   pad pcd/apts into float4 (label -> apts4.w)
// ---------------------------------------------------------------------------
__global__ void __launch_bounds__(128) precompute_kernel(
    const float* __restrict__ feats, const float* __restrict__ w_in,
    const float* __restrict__ b_in, int n_pts,
    const float* __restrict__ w1g, const float* __restrict__ w2g,
    const float* __restrict__ b2g, const float* __restrict__ w_outg,
    const float* __restrict__ b_outg,
    const float* __restrict__ pcd, int nPcd,
    const float* __restrict__ apts, const int* __restrict__ labels, int nApts,
    int gBlocks)
{
    if (blockIdx.x >= (unsigned)(gBlocks + 16)) {
        int i = (blockIdx.x - gBlocks - 16) * 128 + threadIdx.x;
        if (i < nPcd)
            pcd4[i] = make_float4(pcd[3 * i], pcd[3 * i + 1], pcd[3 * i + 2], 0.0f);
        if (i < nApts)
            apts4[i] = make_float4(apts[3 * i], apts[3 * i + 1], apts[3 * i + 2],
                                   (float)labels[i]);
        return;
    }
    if (blockIdx.x >= (unsigned)gBlocks) {
        int idx = (blockIdx.x - gBlocks) * 128 + threadIdx.x;  // 0..2047
        w_pack[idx] = pack_f16x2(w1g[2 * idx], w1g[2 * idx + 1]);
        // block gBlocks additionally computes wf = w2 @ w_out, bf
        if (blockIdx.x == (unsigned)gBlocks) {
            int i = threadIdx.x >> 1;       // 0..63
            int o = threadIdx.x & 1;        // 0..1
            float s = 0.0f;
            for (int k = 0; k < 64; k++)
                s = fmaf(w2g[i * 64 + k], w_outg[k * 2 + o], s);
            wf_buf[i * 2 + o] = s;
            if (threadIdx.x < 2) {
                float sb = b_outg[threadIdx.x];
                for (int k = 0; k < 64; k++)
                    sb = fmaf(b2g[k], w_outg[k * 2 + threadIdx.x], sb);
                bf_buf[threadIdx.x] = sb;
            }
        }
        return;
    }

    __shared__ __align__(16) ull s_w[2048];
    for (int idx = threadIdx.x; idx < 2048; idx += 128)
        s_w[idx] = ((const ull*)w_in)[idx];
    __syncthreads();

    int n = blockIdx.x * 128 + threadIdx.x;
    if (n >= n_pts) return;

    float act[64];
    const float4* fp = (const float4*)(feats + (size_t)n * 64);
#pragma unroll
    for (int i = 0; i < 16; i++) {
        float4 v = fp[i];
        act[4 * i] = v.x; act[4 * i + 1] = v.y; act[4 * i + 2] = v.z; act[4 * i + 3] = v.w;
    }
    ull acc[32];
    const ull* bp = (const ull*)b_in;
#pragma unroll
    for (int j = 0; j < 32; j++) acc[j] = bp[j];
#pragma unroll
    for (int i = 0; i < 64; i++) {
        ull a2 = bcast2(act[i]);
#pragma unroll
        for (int j = 0; j < 32; j += 2) {
            ulonglong2 w = *reinterpret_cast<const ulonglong2*>(&s_w[i * 32 + j]);
            acc[j] = ffma2(a2, w.x, acc[j]);
            acc[j + 1] = ffma2(a2, w.y, acc[j + 1]);
        }
    }
    uint32_t h[32];
#pragma unroll
    for (int j = 0; j < 32; j++) {
        float f0, f1; unpack2(acc[j], f0, f1);
        h[j] = pack_f16x2(f0, f1);
    }
    uint4* gp = (uint4*)(g_buf + (size_t)n * 64);
#pragma unroll
    for (int q = 0; q < 8; q++)
        gp[q] = make_uint4(h[4 * q], h[4 * q + 1], h[4 * q + 2], h[4 * q + 3]);
}

// ---------------------------------------------------------------------------
// Kernel 2: persistent mma.sync edge MLP — layer2+fc_out folded into wf/bf.
// Only ONE 64x64 GEMM (w1) remains on the tensor pipe.
// 128 edges/tile, 4 warps, 32 edges/warp. Cooperative g gather, half2 stage A.
// SMEM (bytes):
//   [0)      w1 tile [64][72 fp16] (144B stride)                      9216
//   [9216)   A tile [128][72] fp16 (144B stride)                      18432
//   [27648)  w3 (3x64 f32)                                            768
//   [28416)  wf (64x2 f32)                                            512
//   [28928)  b1 (64 f32)                                              256
//   [29184)  bf (2 f32)
// ---------------------------------------------------------------------------
#define SM_W     0
#define SM_A     9216
#define SM_W3    27648
#define SM_WF    28416
#define SM_B1    28928
#define SM_BF    29184
#define SM_TOTAL 29440

__global__ void __launch_bounds__(128, 3) edge_mma_kernel(
    const int* __restrict__ row,
    const int* __restrict__ col,
    const float* __restrict__ w_in,
    const float* __restrict__ b1g,
    float* __restrict__ out,
    int nE, int nTiles, int write_labels)
{
    extern __shared__ __align__(16) char smem[];
    const int tid = threadIdx.x;
    const int lane = tid & 31;
    const int warp = tid >> 5;
    const uint32_t FULL = 0xFFFFFFFFu;

    // ---- stage weights into SMEM (144B row stride, conflict-free ldsm) ----
    for (int idx = tid; idx < 2048; idx += 128) {
        int rk = idx >> 5, cc = idx & 31;
        *(uint32_t*)(smem + SM_W + rk * 144 + cc * 4) = w_pack[idx];
    }
    float* s_w3 = (float*)(smem + SM_W3);
    float* s_wf = (float*)(smem + SM_WF);
    float* s_b1 = (float*)(smem + SM_B1);
    float* s_bf = (float*)(smem + SM_BF);
    for (int idx = tid; idx < 192; idx += 128) s_w3[idx] = w_in[64 * 64 + idx];
    if (tid < 128) s_wf[tid] = wf_buf[tid];
    if (tid < 64) s_b1[tid] = b1g[tid];
    if (tid < 2) s_bf[tid] = bf_buf[tid];
    __syncthreads();

    const uint32_t sbase = smem_u32(smem);
    const uint32_t sA = sbase + SM_A;

    const int a_row = (lane & 7) + ((lane >> 3) & 1) * 8;      // 0..15
    const int a_c8 = ((lane >> 4) & 1) * 8;                     // 0 / +8 cols
    const int b_row = (lane & 7) + ((lane >> 3) & 3) * 8;       // 0..31

    // per-lane cooperative-gather mapping + w3 column slice as half2 (constant)
    const int esub = lane >> 3;          // which of 4 edges this lane serves
    const int part = lane & 7;           // which 16B chunk of the row
    __half2 w3h[3][4];
#pragma unroll
    for (int rr = 0; rr < 3; rr++)
#pragma unroll
        for (int p = 0; p < 4; p++)
            w3h[rr][p] = __floats2half2_rn(s_w3[rr * 64 + part * 8 + 2 * p],
                                           s_w3[rr * 64 + part * 8 + 2 * p + 1]);
    const __half2 hzero = __floats2half2_rn(0.0f, 0.0f);

    // preload first tile's indices
    int r = 0, c = 0;
    if (blockIdx.x < nTiles) {
        int e0 = blockIdx.x * 128 + tid;
        int ee = e0 < nE ? e0 : nE - 1;
        r = row[ee]; c = col[ee];
    }

    for (int tile = blockIdx.x; tile < nTiles; tile += gridDim.x) {
        const int e = tile * 128 + tid;
        const bool valid = e < nE;

        // preload next tile's indices (registers only, coalesced)
        int rn = r, cn = c;
        {
            int tn = tile + gridDim.x;
            if (tn < nTiles) {
                int en = tn * 128 + tid;
                int een = en < nE ? en : nE - 1;
                rn = row[een]; cn = col[een];
            }
        }

        const float4 ap = apts4[r];
        const float4 pc = pcd4[c];
        const uint32_t h00 = pack_f16x2(ap.x - pc.x, ap.x - pc.x);
        const uint32_t h11 = pack_f16x2(ap.y - pc.y, ap.y - pc.y);
        const uint32_t h22 = pack_f16x2(ap.z - pc.z, ap.z - pc.z);
        const float lab = ap.w;

        // ---- stage A (cooperative, half2): 8 lanes per edge row.
        //      a = relu(g[c] + pos @ w3) -> fp16 SMEM tile ----
#pragma unroll
        for (int i = 0; i < 8; i++) {
            const int eg = 4 * i + esub;                       // edge-in-warp
            const int cg = __shfl_sync(FULL, c, eg);
            const __half2 q0 = u2h2(__shfl_sync(FULL, h00, eg));
            const __half2 q1 = u2h2(__shfl_sync(FULL, h11, eg));
            const __half2 q2 = u2h2(__shfl_sync(FULL, h22, eg));
            const uint4 v = *(const uint4*)(g_buf + (size_t)cg * 64 + part * 8);
            uint32_t w[4] = {v.x, v.y, v.z, v.w};
            uint32_t h4[4];
#pragma unroll
            for (int p = 0; p < 4; p++) {
                __half2 hv = u2h2(w[p]);
                hv = __hfma2(q0, w3h[0][p], hv);
                hv = __hfma2(q1, w3h[1][p], hv);
                hv = __hfma2(q2, w3h[2][p], hv);
                hv = __hmax2(hv, hzero);
                h4[p] = h2u2(hv);
            }
            asm volatile("st.shared.v4.b32 [%0], {%1,%2,%3,%4};" ::
                         "r"(sA + (uint32_t)(warp * 32 + eg) * 144 + part * 16),
                         "r"(h4[0]), "r"(h4[1]), "r"(h4[2]), "r"(h4[3]));
        }
        __syncwarp();

        // ---- load A fragments ----
        uint32_t A[2][4][4];
#pragma unroll
        for (int mt = 0; mt < 2; mt++) {
            const int rowm = warp * 32 + mt * 16 + a_row;
#pragma unroll
            for (int kt = 0; kt < 4; kt++)
                ldsm_x4(A[mt][kt], sA + (uint32_t)rowm * 144 + (kt * 16 + a_c8) * 2);
        }

        // ===================== single hidden layer (w1) =====================
        float C[2][8][4];
#pragma unroll
        for (int mt = 0; mt < 2; mt++)
#pragma unroll
            for (int nt = 0; nt < 8; nt++)
#pragma unroll
                for (int i = 0; i < 4; i++) C[mt][nt][i] = 0.0f;

#pragma unroll
        for (int kg = 0; kg < 2; kg++) {
#pragma unroll
            for (int nt = 0; nt < 8; nt++) {
                uint32_t B[4];
                ldsm_x4_t(B, sbase + SM_W + (uint32_t)(kg * 32 + b_row) * 144 + nt * 16);
#pragma unroll
                for (int mt = 0; mt < 2; mt++) {
                    mma16816(C[mt][nt], A[mt][2 * kg], B);
                    mma16816(C[mt][nt], A[mt][2 * kg + 1], B + 2);
                }
            }
        }

        // ---- fused epilogue: logits = relu(C + b1) @ wf + bf; softmax ----
#pragma unroll
        for (int mt = 0; mt < 2; mt++) {
            float l0a = 0.0f, l1a = 0.0f, l0b = 0.0f, l1b = 0.0f;
#pragma unroll
            for (int nt = 0; nt < 8; nt++) {
                const int col0 = nt * 8 + (lane & 3) * 2;
                float2 bb = *(const float2*)(s_b1 + col0);
                float4 wo = *(const float4*)(s_wf + 2 * col0);
                float x0 = fmaxf(C[mt][nt][0] + bb.x, 0.0f);
                float x1 = fmaxf(C[mt][nt][1] + bb.y, 0.0f);
                float x2 = fmaxf(C[mt][nt][2] + bb.x, 0.0f);
                float x3 = fmaxf(C[mt][nt][3] + bb.y, 0.0f);
                l0a = fmaf(x0, wo.x, fmaf(x1, wo.z, l0a));
                l1a = fmaf(x0, wo.y, fmaf(x1, wo.w, l1a));
                l0b = fmaf(x2, wo.x, fmaf(x3, wo.z, l0b));
                l1b = fmaf(x2, wo.y, fmaf(x3, wo.w, l1b));
            }
#pragma unroll
            for (int off = 1; off <= 2; off <<= 1) {
                l0a += __shfl_xor_sync(FULL, l0a, off);
                l1a += __shfl_xor_sync(FULL, l1a, off);
                l0b += __shfl_xor_sync(FULL, l0b, off);
                l1b += __shfl_xor_sync(FULL, l1b, off);
            }
            if ((lane & 3) == 0) {
                const int e0 = tile * 128 + warp * 32 + mt * 16 + (lane >> 2);
                float la0 = l0a + s_bf[0], la1 = l1a + s_bf[1];
                float m0 = fmaxf(la0, la1);
                float ea = __expf(la0 - m0), eb = __expf(la1 - m0);
                float inv = 1.0f / (ea + eb);
                if (e0 < nE)
                    *(float2*)(out + 2 * (size_t)e0) = make_float2(ea * inv, eb * inv);

                const int e1 = e0 + 8;
                float lb0 = l0b + s_bf[0], lb1 = l1b + s_bf[1];
                float m1 = fmaxf(lb0, lb1);
                float ec = __expf(lb0 - m1), ed = __expf(lb1 - m1);
                float inv2 = 1.0f / (ec + ed);
                if (e1 < nE)
                    *(float2*)(out + 2 * (size_t)e1) = make_float2(ec * inv2, ed * inv2);
            }
        }

        if (write_labels && valid)
            out[2 * (size_t)nE + e] = lab;

        r = rn; c = cn;
        __syncwarp();   // A-tile rows reused next iteration by this warp only
    }
}

// ---------------------------------------------------------------------------
extern "C" void kernel_launch(void* const* d_in, const int* in_sizes, int n_in,
                              void* d_out, int out_size)
{
    const float* pcd         = (const float*)d_in[0];
    const float* feats       = (const float*)d_in[1];
    const float* also_pts    = (const float*)d_in[2];
    const int*   also_labels = (const int*)d_in[3];
    const int*   row         = (const int*)d_in[4];
    const int*   col         = (const int*)d_in[5];
    const float* w_in        = (const float*)d_in[6];
    const float* b_in        = (const float*)d_in[7];
    const float* w1          = (const float*)d_in[8];
    const float* b1          = (const float*)d_in[9];
    const float* w2          = (const float*)d_in[10];
    const float* b2          = (const float*)d_in[11];
    const float* w_out       = (const float*)d_in[12];
    const float* b_out       = (const float*)d_in[13];

    int nPts = in_sizes[1] / 64;
    if (nPts > 100000) nPts = 100000;
    int nPcd = in_sizes[0] / 3;
    if (nPcd > 100000) nPcd = 100000;
    int nApts = in_sizes[2] / 3;
    if (nApts > 100000) nApts = 100000;
    int nE = in_sizes[4];
    int nTiles = (nE + 127) / 128;
    int write_labels = ((long long)out_size >= 3LL * nE) ? 1 : 0;

    static int attr_done = 0;
    if (!attr_done) {
        cudaFuncSetAttribute(edge_mma_kernel,
                             cudaFuncAttributeMaxDynamicSharedMemorySize, SM_TOTAL);
        attr_done = 1;
    }

    int gBlocks = (nPts + 127) / 128;
    int nmax = nPcd > nApts ? nPcd : nApts;
    int padBlocks = (nmax + 127) / 128;
    precompute_kernel<<<gBlocks + 16 + padBlocks, 128>>>(
        feats, w_in, b_in, nPts, w1, w2, b2, w_out, b_out,
        pcd, nPcd, also_pts, also_labels, nApts, gBlocks);

    int grid = 148 * 3;
    if (grid > nTiles) grid = nTiles;
    edge_mma_kernel<<<grid, 128, SM_TOTAL>>>(row, col, w_in, b1,
                                             (float*)d_out, nE, nTiles, write_labels);
}

// round 14
// speedup vs baseline: 1.2931x; 1.0330x over previous
#include <cuda_runtime.h>
#include <cuda_fp16.h>
#include <cstdint>

typedef unsigned long long ull;

// Precomputed g = feats @ w_in[0:64,:] + b_in  (N x 64), stored fp16
__device__ __half g_buf[100000 * 64];
// Packed fp16 weights: w1 only (64x64 fp16 = 2048 u32)
__device__ uint32_t w_pack[2048];
// Fused output weights: wf = w2 @ w_out (64x2 f32), bf = b2 @ w_out + b_out
__device__ float wf_buf[128];
__device__ float bf_buf[2];
// float4-padded points; apts4.w carries the label as float
__device__ float4 pcd4[100000];
__device__ float4 apts4[100000];

// ---------------------------------------------------------------------------
// helpers
// ---------------------------------------------------------------------------
__device__ __forceinline__ ull pack2(float lo, float hi) {
    ull r; asm("mov.b64 %0, {%1, %2};" : "=l"(r) : "f"(lo), "f"(hi)); return r;
}
__device__ __forceinline__ ull bcast2(float v) { return pack2(v, v); }
__device__ __forceinline__ ull ffma2(ull a, ull b, ull c) {
    ull d; asm("fma.rn.f32x2 %0, %1, %2, %3;" : "=l"(d) : "l"(a), "l"(b), "l"(c)); return d;
}
__device__ __forceinline__ void unpack2(ull v, float& lo, float& hi) {
    asm("mov.b64 {%0, %1}, %2;" : "=f"(lo), "=f"(hi) : "l"(v));
}
__device__ __forceinline__ uint32_t smem_u32(const void* p) {
    uint32_t a;
    asm("{ .reg .u64 t; cvta.to.shared.u64 t, %1; cvt.u32.u64 %0, t; }" : "=r"(a) : "l"(p));
    return a;
}
__device__ __forceinline__ uint32_t pack_f16x2(float lo, float hi) {
    __half2 h = __floats2half2_rn(lo, hi);      // lo -> low half
    return *reinterpret_cast<uint32_t*>(&h);
}
__device__ __forceinline__ __half2 u2h2(uint32_t v) {
    return *reinterpret_cast<__half2*>(&v);
}
__device__ __forceinline__ uint32_t h2u2(__half2 v) {
    return *reinterpret_cast<uint32_t*>(&v);
}
__device__ __forceinline__ void ldsm_x4(uint32_t* r, uint32_t addr) {
    asm volatile("ldmatrix.sync.aligned.m8n8.x4.shared.b16 {%0,%1,%2,%3}, [%4];"
                 : "=r"(r[0]), "=r"(r[1]), "=r"(r[2]), "=r"(r[3]) : "r"(addr));
}
__device__ __forceinline__ void ldsm_x4_t(uint32_t* r, uint32_t addr) {
    asm volatile("ldmatrix.sync.aligned.m8n8.x4.trans.shared.b16 {%0,%1,%2,%3}, [%4];"
                 : "=r"(r[0]), "=r"(r[1]), "=r"(r[2]), "=r"(r[3]) : "r"(addr));
}
__device__ __forceinline__ void mma16816(float* c, const uint32_t* a, const uint32_t* b) {
    asm volatile(
        "mma.sync.aligned.m16n8k16.row.col.f32.f16.f16.f32 "
        "{%0,%1,%2,%3}, {%4,%5,%6,%7}, {%8,%9}, {%0,%1,%2,%3};"
        : "+f"(c[0]), "+f"(c[1]), "+f"(c[2]), "+f"(c[3])
        : "r"(a[0]), "r"(a[1]), "r"(a[2]), "r"(a[3]), "r"(b[0]), "r"(b[1]));
}

// ---------------------------------------------------------------------------
// Kernel 1 (fused prologue):
//   blocks [0, G):        g[n,:] = fp16(feats[n,:] @ w_in[0:64,:] + b_in)
//   blocks [G, G+16):     fp16 conversion of w1; block G also builds wf/bf
//   blocks [G+16, end):   pad pcd/apts into float4 (label -> apts4.w)
// ---------------------------------------------------------------------------
__global__ void __launch_bounds__(128) precompute_kernel(
    const float* __restrict__ feats, const float* __restrict__ w_in,
    const float* __restrict__ b_in, int n_pts,
    const float* __restrict__ w1g, const float* __restrict__ w2g,
    const float* __restrict__ b2g, const float* __restrict__ w_outg,
    const float* __restrict__ b_outg,
    const float* __restrict__ pcd, int nPcd,
    const float* __restrict__ apts, const int* __restrict__ labels, int nApts,
    int gBlocks)
{
    if (blockIdx.x >= (unsigned)(gBlocks + 16)) {
        int i = (blockIdx.x - gBlocks - 16) * 128 + threadIdx.x;
        if (i < nPcd)
            pcd4[i] = make_float4(pcd[3 * i], pcd[3 * i + 1], pcd[3 * i + 2], 0.0f);
        if (i < nApts)
            apts4[i] = make_float4(apts[3 * i], apts[3 * i + 1], apts[3 * i + 2],
                                   (float)labels[i]);
        return;
    }
    if (blockIdx.x >= (unsigned)gBlocks) {
        int idx = (blockIdx.x - gBlocks) * 128 + threadIdx.x;  // 0..2047
        w_pack[idx] = pack_f16x2(w1g[2 * idx], w1g[2 * idx + 1]);
        // block gBlocks additionally computes wf = w2 @ w_out, bf
        if (blockIdx.x == (unsigned)gBlocks) {
            int i = threadIdx.x >> 1;       // 0..63
            int o = threadIdx.x & 1;        // 0..1
            float s = 0.0f;
            for (int k = 0; k < 64; k++)
                s = fmaf(w2g[i * 64 + k], w_outg[k * 2 + o], s);
            wf_buf[i * 2 + o] = s;
            if (threadIdx.x < 2) {
                float sb = b_outg[threadIdx.x];
                for (int k = 0; k < 64; k++)
                    sb = fmaf(b2g[k], w_outg[k * 2 + threadIdx.x], sb);
                bf_buf[threadIdx.x] = sb;
            }
        }
        return;
    }

    __shared__ __align__(16) ull s_w[2048];
    for (int idx = threadIdx.x; idx < 2048; idx += 128)
        s_w[idx] = ((const ull*)w_in)[idx];
    __syncthreads();

    int n = blockIdx.x * 128 + threadIdx.x;
    if (n >= n_pts) return;

    float act[64];
    const float4* fp = (const float4*)(feats + (size_t)n * 64);
#pragma unroll
    for (int i = 0; i < 16; i++) {
        float4 v = fp[i];
        act[4 * i] = v.x; act[4 * i + 1] = v.y; act[4 * i + 2] = v.z; act[4 * i + 3] = v.w;
    }
    ull acc[32];
    const ull* bp = (const ull*)b_in;
#pragma unroll
    for (int j = 0; j < 32; j++) acc[j] = bp[j];
#pragma unroll
    for (int i = 0; i < 64; i++) {
        ull a2 = bcast2(act[i]);
#pragma unroll
        for (int j = 0; j < 32; j += 2) {
            ulonglong2 w = *reinterpret_cast<const ulonglong2*>(&s_w[i * 32 + j]);
            acc[j] = ffma2(a2, w.x, acc[j]);
            acc[j + 1] = ffma2(a2, w.y, acc[j + 1]);
        }
    }
    uint32_t h[32];
#pragma unroll
    for (int j = 0; j < 32; j++) {
        float f0, f1; unpack2(acc[j], f0, f1);
        h[j] = pack_f16x2(f0, f1);
    }
    uint4* gp = (uint4*)(g_buf + (size_t)n * 64);
#pragma unroll
    for (int q = 0; q < 8; q++)
        gp[q] = make_uint4(h[4 * q], h[4 * q + 1], h[4 * q + 2], h[4 * q + 3]);
}

// ---------------------------------------------------------------------------
// Kernel 2: persistent mma.sync edge MLP — layer1 GEMM + tensor-core wf
// projection (n=8 zero-padded). No shuffle reduction.
// 128 edges/tile, 4 warps, 32 edges/warp. Cooperative g gather, half2 stage A.
// SMEM (bytes):
//   [0)      w1 tile [64][72 fp16] (144B stride)                      9216
//   [9216)   A tile [128][72] fp16 (144B stride)                      18432
//   [27648)  w3 (3x64 f32)                                            768
//   [28416)  wf16 tile [64][8 fp16] (16B stride)                      1024
//   [29440)  b1 (64 f32)                                              256
//   [29696)  bf (2 f32)
// ---------------------------------------------------------------------------
#define SM_W     0
#define SM_A     9216
#define SM_W3    27648
#define SM_WF16  28416
#define SM_B1    29440
#define SM_BF    29696
#define SM_TOTAL 29952

__global__ void __launch_bounds__(128, 3) edge_mma_kernel(
    const int* __restrict__ row,
    const int* __restrict__ col,
    const float* __restrict__ w_in,
    const float* __restrict__ b1g,
    float* __restrict__ out,
    int nE, int nTiles, int write_labels)
{
    extern __shared__ __align__(16) char smem[];
    const int tid = threadIdx.x;
    const int lane = tid & 31;
    const int warp = tid >> 5;
    const uint32_t FULL = 0xFFFFFFFFu;

    // ---- stage weights into SMEM ----
    for (int idx = tid; idx < 2048; idx += 128) {
        int rk = idx >> 5, cc = idx & 31;
        *(uint32_t*)(smem + SM_W + rk * 144 + cc * 4) = w_pack[idx];
    }
    float* s_w3 = (float*)(smem + SM_W3);
    __half* s_wf16 = (__half*)(smem + SM_WF16);
    float* s_b1 = (float*)(smem + SM_B1);
    float* s_bf = (float*)(smem + SM_BF);
    for (int idx = tid; idx < 192; idx += 128) s_w3[idx] = w_in[64 * 64 + idx];
    // wf16: [64 k-rows][8 n-cols], cols 0,1 = wf, cols 2..7 = 0
    if (tid < 128) {
        int k = tid >> 1, o = tid & 1;
        s_wf16[k * 8 + o] = __float2half_rn(wf_buf[k * 2 + o]);
    }
    {
        // zero cols 2..7
        int idx = tid;                 // 64 rows x 6 cols = 384 entries
        for (; idx < 384; idx += 128) {
            int k = idx / 6, o = 2 + idx % 6;
            s_wf16[k * 8 + o] = __float2half_rn(0.0f);
        }
    }
    if (tid < 64) s_b1[tid] = b1g[tid];
    if (tid < 2) s_bf[tid] = bf_buf[tid];
    __syncthreads();

    const uint32_t sbase = smem_u32(smem);
    const uint32_t sA = sbase + SM_A;

    const int a_row = (lane & 7) + ((lane >> 3) & 1) * 8;      // 0..15
    const int a_c8 = ((lane >> 4) & 1) * 8;                     // 0 / +8 cols
    const int b_row = (lane & 7) + ((lane >> 3) & 3) * 8;       // 0..31

    // hoisted wf B fragments (tile-invariant): 2 kg x 4 regs
    uint32_t BF[2][4];
#pragma unroll
    for (int kg = 0; kg < 2; kg++)
        ldsm_x4_t(BF[kg], sbase + SM_WF16 + (uint32_t)(kg * 32 + b_row) * 16);

    // per-lane cooperative-gather mapping + w3 column slice as half2 (constant)
    const int esub = lane >> 3;          // which of 4 edges this lane serves
    const int part = lane & 7;           // which 16B chunk of the row
    __half2 w3h[3][4];
#pragma unroll
    for (int rr = 0; rr < 3; rr++)
#pragma unroll
        for (int p = 0; p < 4; p++)
            w3h[rr][p] = __floats2half2_rn(s_w3[rr * 64 + part * 8 + 2 * p],
                                           s_w3[rr * 64 + part * 8 + 2 * p + 1]);
    const __half2 hzero = __floats2half2_rn(0.0f, 0.0f);

    // preload first tile's indices
    int r = 0, c = 0;
    if (blockIdx.x < nTiles) {
        int e0 = blockIdx.x * 128 + tid;
        int ee = e0 < nE ? e0 : nE - 1;
        r = row[ee]; c = col[ee];
    }

    for (int tile = blockIdx.x; tile < nTiles; tile += gridDim.x) {
        const int e = tile * 128 + tid;
        const bool valid = e < nE;

        // preload next tile's indices (registers only, coalesced)
        int rn = r, cn = c;
        {
            int tn = tile + gridDim.x;
            if (tn < nTiles) {
                int en = tn * 128 + tid;
                int een = en < nE ? en : nE - 1;
                rn = row[een]; cn = col[een];
            }
        }

        const float4 ap = apts4[r];
        const float4 pc = pcd4[c];
        const uint32_t h00 = pack_f16x2(ap.x - pc.x, ap.x - pc.x);
        const uint32_t h11 = pack_f16x2(ap.y - pc.y, ap.y - pc.y);
        const uint32_t h22 = pack_f16x2(ap.z - pc.z, ap.z - pc.z);
        const float lab = ap.w;

        // ---- stage A (cooperative, half2): 8 lanes per edge row ----
#pragma unroll
        for (int i = 0; i < 8; i++) {
            const int eg = 4 * i + esub;                       // edge-in-warp
            const int cg = __shfl_sync(FULL, c, eg);
            const __half2 q0 = u2h2(__shfl_sync(FULL, h00, eg));
            const __half2 q1 = u2h2(__shfl_sync(FULL, h11, eg));
            const __half2 q2 = u2h2(__shfl_sync(FULL, h22, eg));
            const uint4 v = *(const uint4*)(g_buf + (size_t)cg * 64 + part * 8);
            uint32_t w[4] = {v.x, v.y, v.z, v.w};
            uint32_t h4[4];
#pragma unroll
            for (int p = 0; p < 4; p++) {
                __half2 hv = u2h2(w[p]);
                hv = __hfma2(q0, w3h[0][p], hv);
                hv = __hfma2(q1, w3h[1][p], hv);
                hv = __hfma2(q2, w3h[2][p], hv);
                hv = __hmax2(hv, hzero);
                h4[p] = h2u2(hv);
            }
            asm volatile("st.shared.v4.b32 [%0], {%1,%2,%3,%4};" ::
                         "r"(sA + (uint32_t)(warp * 32 + eg) * 144 + part * 16),
                         "r"(h4[0]), "r"(h4[1]), "r"(h4[2]), "r"(h4[3]));
        }
        __syncwarp();

        // ---- load A fragments ----
        uint32_t A[2][4][4];
#pragma unroll
        for (int mt = 0; mt < 2; mt++) {
            const int rowm = warp * 32 + mt * 16 + a_row;
#pragma unroll
            for (int kt = 0; kt < 4; kt++)
                ldsm_x4(A[mt][kt], sA + (uint32_t)rowm * 144 + (kt * 16 + a_c8) * 2);
        }

        // ===================== hidden layer (w1) =====================
        float C[2][8][4];
#pragma unroll
        for (int mt = 0; mt < 2; mt++)
#pragma unroll
            for (int nt = 0; nt < 8; nt++)
#pragma unroll
                for (int i = 0; i < 4; i++) C[mt][nt][i] = 0.0f;

#pragma unroll
        for (int kg = 0; kg < 2; kg++) {
#pragma unroll
            for (int nt = 0; nt < 8; nt++) {
                uint32_t B[4];
                ldsm_x4_t(B, sbase + SM_W + (uint32_t)(kg * 32 + b_row) * 144 + nt * 16);
#pragma unroll
                for (int mt = 0; mt < 2; mt++) {
                    mma16816(C[mt][nt], A[mt][2 * kg], B);
                    mma16816(C[mt][nt], A[mt][2 * kg + 1], B + 2);
                }
            }
        }

        // ---- tensor-core epilogue: logits = relu(C + b1) @ wf16 + bf ----
#pragma unroll
        for (int mt = 0; mt < 2; mt++) {
            uint32_t A2[4][4];
#pragma unroll
            for (int kt = 0; kt < 4; kt++) {
#pragma unroll
                for (int half = 0; half < 2; half++) {
                    const int nt = 2 * kt + half;
                    const int col0 = nt * 8 + (lane & 3) * 2;
                    float2 bb = *(const float2*)(s_b1 + col0);
                    A2[kt][2 * half + 0] =
                        pack_f16x2(fmaxf(C[mt][nt][0] + bb.x, 0.0f),
                                   fmaxf(C[mt][nt][1] + bb.y, 0.0f));
                    A2[kt][2 * half + 1] =
                        pack_f16x2(fmaxf(C[mt][nt][2] + bb.x, 0.0f),
                                   fmaxf(C[mt][nt][3] + bb.y, 0.0f));
                }
            }
            float L[4] = {0.0f, 0.0f, 0.0f, 0.0f};
#pragma unroll
            for (int kg = 0; kg < 2; kg++) {
                mma16816(L, A2[2 * kg], BF[kg]);
                mma16816(L, A2[2 * kg + 1], BF[kg] + 2);
            }
            // lanes with (lane&3)==0 hold cols 0,1 = logits for rows
            // lane>>2 and lane>>2 + 8
            if ((lane & 3) == 0) {
                const int e0 = tile * 128 + warp * 32 + mt * 16 + (lane >> 2);
                float la0 = L[0] + s_bf[0], la1 = L[1] + s_bf[1];
                float m0 = fmaxf(la0, la1);
                float ea = __expf(la0 - m0), eb = __expf(la1 - m0);
                float inv = 1.0f / (ea + eb);
                if (e0 < nE)
                    *(float2*)(out + 2 * (size_t)e0) = make_float2(ea * inv, eb * inv);

                const int e1 = e0 + 8;
                float lb0 = L[2] + s_bf[0], lb1 = L[3] + s_bf[1];
                float m1 = fmaxf(lb0, lb1);
                float ec = __expf(lb0 - m1), ed = __expf(lb1 - m1);
                float inv2 = 1.0f / (ec + ed);
                if (e1 < nE)
                    *(float2*)(out + 2 * (size_t)e1) = make_float2(ec * inv2, ed * inv2);
            }
        }

        if (write_labels && valid)
            out[2 * (size_t)nE + e] = lab;

        r = rn; c = cn;
        __syncwarp();   // A-tile rows reused next iteration by this warp only
    }
}

// ---------------------------------------------------------------------------
extern "C" void kernel_launch(void* const* d_in, const int* in_sizes, int n_in,
                              void* d_out, int out_size)
{
    const float* pcd         = (const float*)d_in[0];
    const float* feats       = (const float*)d_in[1];
    const float* also_pts    = (const float*)d_in[2];
    const int*   also_labels = (const int*)d_in[3];
    const int*   row         = (const int*)d_in[4];
    const int*   col         = (const int*)d_in[5];
    const float* w_in        = (const float*)d_in[6];
    const float* b_in        = (const float*)d_in[7];
    const float* w1          = (const float*)d_in[8];
    const float* b1          = (const float*)d_in[9];
    const float* w2          = (const float*)d_in[10];
    const float* b2          = (const float*)d_in[11];
    const float* w_out       = (const float*)d_in[12];
    const float* b_out       = (const float*)d_in[13];

    int nPts = in_sizes[1] / 64;
    if (nPts > 100000) nPts = 100000;
    int nPcd = in_sizes[0] / 3;
    if (nPcd > 100000) nPcd = 100000;
    int nApts = in_sizes[2] / 3;
    if (nApts > 100000) nApts = 100000;
    int nE = in_sizes[4];
    int nTiles = (nE + 127) / 128;
    int write_labels = ((long long)out_size >= 3LL * nE) ? 1 : 0;

    static int attr_done = 0;
    if (!attr_done) {
        cudaFuncSetAttribute(edge_mma_kernel,
                             cudaFuncAttributeMaxDynamicSharedMemorySize, SM_TOTAL);
        attr_done = 1;
    }

    int gBlocks = (nPts + 127) / 128;
    int nmax = nPcd > nApts ? nPcd : nApts;
    int padBlocks = (nmax + 127) / 128;
    precompute_kernel<<<gBlocks + 16 + padBlocks, 128>>>(
        feats, w_in, b_in, nPts, w1, w2, b2, w_out, b_out,
        pcd, nPcd, also_pts, also_labels, nApts, gBlocks);

    int grid = 148 * 3;
    if (grid > nTiles) grid = nTiles;
    edge_mma_kernel<<<grid, 128, SM_TOTAL>>>(row, col, w_in, b1,
                                             (float*)d_out, nE, nTiles, write_labels);
}

// round 15
// speedup vs baseline: 1.3173x; 1.0187x over previous
#include <cuda_runtime.h>
#include <cuda_fp16.h>
#include <cstdint>

typedef unsigned long long ull;

// Precomputed g = feats @ w_in[0:64,:] + b_in  (N x 64), stored fp16
__device__ __half g_buf[100000 * 64];
// Packed fp16 weights: w1 only (64x64 fp16 = 2048 u32)
__device__ uint32_t w_pack[2048];
// Fused output weights: wf = w2 @ w_out (64x2 f32), bf = b2 @ w_out + b_out
__device__ float wf_buf[128];
__device__ float bf_buf[2];
// float4-padded points; apts4.w carries the label as float
__device__ float4 pcd4[100000];
__device__ float4 apts4[100000];

// ---------------------------------------------------------------------------
// helpers
// ---------------------------------------------------------------------------
__device__ __forceinline__ ull pack2(float lo, float hi) {
    ull r; asm("mov.b64 %0, {%1, %2};" : "=l"(r) : "f"(lo), "f"(hi)); return r;
}
__device__ __forceinline__ ull bcast2(float v) { return pack2(v, v); }
__device__ __forceinline__ ull ffma2(ull a, ull b, ull c) {
    ull d; asm("fma.rn.f32x2 %0, %1, %2, %3;" : "=l"(d) : "l"(a), "l"(b), "l"(c)); return d;
}
__device__ __forceinline__ void unpack2(ull v, float& lo, float& hi) {
    asm("mov.b64 {%0, %1}, %2;" : "=f"(lo), "=f"(hi) : "l"(v));
}
__device__ __forceinline__ uint32_t smem_u32(const void* p) {
    uint32_t a;
    asm("{ .reg .u64 t; cvta.to.shared.u64 t, %1; cvt.u32.u64 %0, t; }" : "=r"(a) : "l"(p));
    return a;
}
__device__ __forceinline__ uint32_t pack_f16x2(float lo, float hi) {
    __half2 h = __floats2half2_rn(lo, hi);      // lo -> low half
    return *reinterpret_cast<uint32_t*>(&h);
}
__device__ __forceinline__ __half2 u2h2(uint32_t v) {
    return *reinterpret_cast<__half2*>(&v);
}
__device__ __forceinline__ uint32_t h2u2(__half2 v) {
    return *reinterpret_cast<uint32_t*>(&v);
}
__device__ __forceinline__ void ldsm_x4(uint32_t* r, uint32_t addr) {
    asm volatile("ldmatrix.sync.aligned.m8n8.x4.shared.b16 {%0,%1,%2,%3}, [%4];"
                 : "=r"(r[0]), "=r"(r[1]), "=r"(r[2]), "=r"(r[3]) : "r"(addr));
}
__device__ __forceinline__ void ldsm_x4_t(uint32_t* r, uint32_t addr) {
    asm volatile("ldmatrix.sync.aligned.m8n8.x4.trans.shared.b16 {%0,%1,%2,%3}, [%4];"
                 : "=r"(r[0]), "=r"(r[1]), "=r"(r[2]), "=r"(r[3]) : "r"(addr));
}
__device__ __forceinline__ void mma16816(float* c, const uint32_t* a, const uint32_t* b) {
    asm volatile(
        "mma.sync.aligned.m16n8k16.row.col.f32.f16.f16.f32 "
        "{%0,%1,%2,%3}, {%4,%5,%6,%7}, {%8,%9}, {%0,%1,%2,%3};"
        : "+f"(c[0]), "+f"(c[1]), "+f"(c[2]), "+f"(c[3])
        : "r"(a[0]), "r"(a[1]), "r"(a[2]), "r"(a[3]), "r"(b[0]), "r"(b[1]));
}

// ---------------------------------------------------------------------------
// Kernel 1 (fused prologue):
//   blocks [0, G):        g[n,:] = fp16(feats[n,:] @ w_in[0:64,:] + b_in)
//   blocks [G, G+16):     fp16 conversion of w1; block G also builds wf/bf
//   blocks [G+16, end):   pad pcd/apts into float4 (label -> apts4.w)
// ---------------------------------------------------------------------------
__global__ void __launch_bounds__(128) precompute_kernel(
    const float* __restrict__ feats, const float* __restrict__ w_in,
    const float* __restrict__ b_in, int n_pts,
    const float* __restrict__ w1g, const float* __restrict__ w2g,
    const float* __restrict__ b2g, const float* __restrict__ w_outg,
    const float* __restrict__ b_outg,
    const float* __restrict__ pcd, int nPcd,
    const float* __restrict__ apts, const int* __restrict__ labels, int nApts,
    int gBlocks)
{
    if (blockIdx.x >= (unsigned)(gBlocks + 16)) {
        int i = (blockIdx.x - gBlocks - 16) * 128 + threadIdx.x;
        if (i < nPcd)
            pcd4[i] = make_float4(pcd[3 * i], pcd[3 * i + 1], pcd[3 * i + 2], 0.0f);
        if (i < nApts)
            apts4[i] = make_float4(apts[3 * i], apts[3 * i + 1], apts[3 * i + 2],
                                   (float)labels[i]);
        return;
    }
    if (blockIdx.x >= (unsigned)gBlocks) {
        int idx = (blockIdx.x - gBlocks) * 128 + threadIdx.x;  // 0..2047
        w_pack[idx] = pack_f16x2(w1g[2 * idx], w1g[2 * idx + 1]);
        // block gBlocks additionally computes wf = w2 @ w_out, bf
        if (blockIdx.x == (unsigned)gBlocks) {
            int i = threadIdx.x >> 1;       // 0..63
            int o = threadIdx.x & 1;        // 0..1
            float s = 0.0f;
            for (int k = 0; k < 64; k++)
                s = fmaf(w2g[i * 64 + k], w_outg[k * 2 + o], s);
            wf_buf[i * 2 + o] = s;
            if (threadIdx.x < 2) {
                float sb = b_outg[threadIdx.x];
                for (int k = 0; k < 64; k++)
                    sb = fmaf(b2g[k], w_outg[k * 2 + threadIdx.x], sb);
                bf_buf[threadIdx.x] = sb;
            }
        }
        return;
    }

    __shared__ __align__(16) ull s_w[2048];
    for (int idx = threadIdx.x; idx < 2048; idx += 128)
        s_w[idx] = ((const ull*)w_in)[idx];
    __syncthreads();

    int n = blockIdx.x * 128 + threadIdx.x;
    if (n >= n_pts) return;

    float act[64];
    const float4* fp = (const float4*)(feats + (size_t)n * 64);
#pragma unroll
    for (int i = 0; i < 16; i++) {
        float4 v = fp[i];
        act[4 * i] = v.x; act[4 * i + 1] = v.y; act[4 * i + 2] = v.z; act[4 * i + 3] = v.w;
    }
    ull acc[32];
    const ull* bp = (const ull*)b_in;
#pragma unroll
    for (int j = 0; j < 32; j++) acc[j] = bp[j];
#pragma unroll
    for (int i = 0; i < 64; i++) {
        ull a2 = bcast2(act[i]);
#pragma unroll
        for (int j = 0; j < 32; j += 2) {
            ulonglong2 w = *reinterpret_cast<const ulonglong2*>(&s_w[i * 32 + j]);
            acc[j] = ffma2(a2, w.x, acc[j]);
            acc[j + 1] = ffma2(a2, w.y, acc[j + 1]);
        }
    }
    uint32_t h[32];
#pragma unroll
    for (int j = 0; j < 32; j++) {
        float f0, f1; unpack2(acc[j], f0, f1);
        h[j] = pack_f16x2(f0, f1);
    }
    uint4* gp = (uint4*)(g_buf + (size_t)n * 64);
#pragma unroll
    for (int q = 0; q < 8; q++)
        gp[q] = make_uint4(h[4 * q], h[4 * q + 1], h[4 * q + 2], h[4 * q + 3]);
}

// ---------------------------------------------------------------------------
// Kernel 2: persistent mma.sync edge MLP — layer1 GEMM + tensor-core wf
// projection. The two 16-edge m-tiles are processed SEQUENTIALLY per warp
// (halves live registers -> 4 CTAs/SM; B-ldsm is cheap post layer-fold).
// SMEM (bytes):
//   [0)      w1 tile [64][72 fp16] (144B stride)                      9216
//   [9216)   A tile [128][72] fp16 (144B stride)                      18432
//   [27648)  w3 (3x64 f32)                                            768
//   [28416)  wf16 tile [64][8 fp16] (16B stride)                      1024
//   [29440)  b1 (64 f32)                                              256
//   [29696)  bf (2 f32)
// ---------------------------------------------------------------------------
#define SM_W     0
#define SM_A     9216
#define SM_W3    27648
#define SM_WF16  28416
#define SM_B1    29440
#define SM_BF    29696
#define SM_TOTAL 29952

__global__ void __launch_bounds__(128, 4) edge_mma_kernel(
    const int* __restrict__ row,
    const int* __restrict__ col,
    const float* __restrict__ w_in,
    const float* __restrict__ b1g,
    float* __restrict__ out,
    int nE, int nTiles, int write_labels)
{
    extern __shared__ __align__(16) char smem[];
    const int tid = threadIdx.x;
    const int lane = tid & 31;
    const int warp = tid >> 5;
    const uint32_t FULL = 0xFFFFFFFFu;

    // ---- stage weights into SMEM ----
    for (int idx = tid; idx < 2048; idx += 128) {
        int rk = idx >> 5, cc = idx & 31;
        *(uint32_t*)(smem + SM_W + rk * 144 + cc * 4) = w_pack[idx];
    }
    float* s_w3 = (float*)(smem + SM_W3);
    __half* s_wf16 = (__half*)(smem + SM_WF16);
    float* s_b1 = (float*)(smem + SM_B1);
    float* s_bf = (float*)(smem + SM_BF);
    for (int idx = tid; idx < 192; idx += 128) s_w3[idx] = w_in[64 * 64 + idx];
    // wf16: [64 k-rows][8 n-cols], cols 0,1 = wf, cols 2..7 = 0
    if (tid < 128) {
        int k = tid >> 1, o = tid & 1;
        s_wf16[k * 8 + o] = __float2half_rn(wf_buf[k * 2 + o]);
    }
    {
        // zero cols 2..7
        int idx = tid;                 // 64 rows x 6 cols = 384 entries
        for (; idx < 384; idx += 128) {
            int k = idx / 6, o = 2 + idx % 6;
            s_wf16[k * 8 + o] = __float2half_rn(0.0f);
        }
    }
    if (tid < 64) s_b1[tid] = b1g[tid];
    if (tid < 2) s_bf[tid] = bf_buf[tid];
    __syncthreads();

    const uint32_t sbase = smem_u32(smem);
    const uint32_t sA = sbase + SM_A;

    const int a_row = (lane & 7) + ((lane >> 3) & 1) * 8;      // 0..15
    const int a_c8 = ((lane >> 4) & 1) * 8;                     // 0 / +8 cols
    const int b_row = (lane & 7) + ((lane >> 3) & 3) * 8;       // 0..31

    // hoisted wf B fragments (tile-invariant): 2 kg x 4 regs
    uint32_t BF[2][4];
#pragma unroll
    for (int kg = 0; kg < 2; kg++)
        ldsm_x4_t(BF[kg], sbase + SM_WF16 + (uint32_t)(kg * 32 + b_row) * 16);

    // per-lane cooperative-gather mapping + w3 column slice as half2 (constant)
    const int esub = lane >> 3;          // which of 4 edges this lane serves
    const int part = lane & 7;           // which 16B chunk of the row
    __half2 w3h[3][4];
#pragma unroll
    for (int rr = 0; rr < 3; rr++)
#pragma unroll
        for (int p = 0; p < 4; p++)
            w3h[rr][p] = __floats2half2_rn(s_w3[rr * 64 + part * 8 + 2 * p],
                                           s_w3[rr * 64 + part * 8 + 2 * p + 1]);
    const __half2 hzero = __floats2half2_rn(0.0f, 0.0f);

    // preload first tile's indices
    int r = 0, c = 0;
    if (blockIdx.x < nTiles) {
        int e0 = blockIdx.x * 128 + tid;
        int ee = e0 < nE ? e0 : nE - 1;
        r = row[ee]; c = col[ee];
    }

    for (int tile = blockIdx.x; tile < nTiles; tile += gridDim.x) {
        const int e = tile * 128 + tid;
        const bool valid = e < nE;

        // preload next tile's indices (registers only, coalesced)
        int rn = r, cn = c;
        {
            int tn = tile + gridDim.x;
            if (tn < nTiles) {
                int en = tn * 128 + tid;
                int een = en < nE ? en : nE - 1;
                rn = row[een]; cn = col[een];
            }
        }

        const float4 ap = apts4[r];
        const float4 pc = pcd4[c];
        const uint32_t h00 = pack_f16x2(ap.x - pc.x, ap.x - pc.x);
        const uint32_t h11 = pack_f16x2(ap.y - pc.y, ap.y - pc.y);
        const uint32_t h22 = pack_f16x2(ap.z - pc.z, ap.z - pc.z);
        const float lab = ap.w;

        // ---- stage A (cooperative, half2): 8 lanes per edge row ----
#pragma unroll
        for (int i = 0; i < 8; i++) {
            const int eg = 4 * i + esub;                       // edge-in-warp
            const int cg = __shfl_sync(FULL, c, eg);
            const __half2 q0 = u2h2(__shfl_sync(FULL, h00, eg));
            const __half2 q1 = u2h2(__shfl_sync(FULL, h11, eg));
            const __half2 q2 = u2h2(__shfl_sync(FULL, h22, eg));
            const uint4 v = *(const uint4*)(g_buf + (size_t)cg * 64 + part * 8);
            uint32_t w[4] = {v.x, v.y, v.z, v.w};
            uint32_t h4[4];
#pragma unroll
            for (int p = 0; p < 4; p++) {
                __half2 hv = u2h2(w[p]);
                hv = __hfma2(q0, w3h[0][p], hv);
                hv = __hfma2(q1, w3h[1][p], hv);
                hv = __hfma2(q2, w3h[2][p], hv);
                hv = __hmax2(hv, hzero);
                h4[p] = h2u2(hv);
            }
            asm volatile("st.shared.v4.b32 [%0], {%1,%2,%3,%4};" ::
                         "r"(sA + (uint32_t)(warp * 32 + eg) * 144 + part * 16),
                         "r"(h4[0]), "r"(h4[1]), "r"(h4[2]), "r"(h4[3]));
        }
        __syncwarp();

        // ==== process the two 16-edge m-tiles sequentially (reg pressure) ====
#pragma unroll 1
        for (int mt = 0; mt < 2; mt++) {
            // ---- load A fragments ----
            uint32_t A[4][4];
            {
                const int rowm = warp * 32 + mt * 16 + a_row;
#pragma unroll
                for (int kt = 0; kt < 4; kt++)
                    ldsm_x4(A[kt], sA + (uint32_t)rowm * 144 + (kt * 16 + a_c8) * 2);
            }

            // ---- hidden layer (w1) ----
            float C[8][4];
#pragma unroll
            for (int nt = 0; nt < 8; nt++)
#pragma unroll
                for (int i = 0; i < 4; i++) C[nt][i] = 0.0f;

#pragma unroll
            for (int kg = 0; kg < 2; kg++) {
#pragma unroll
                for (int nt = 0; nt < 8; nt++) {
                    uint32_t B[4];
                    ldsm_x4_t(B, sbase + SM_W + (uint32_t)(kg * 32 + b_row) * 144 + nt * 16);
                    mma16816(C[nt], A[2 * kg], B);
                    mma16816(C[nt], A[2 * kg + 1], B + 2);
                }
            }

            // ---- tensor-core epilogue: logits = relu(C + b1) @ wf16 + bf ----
            // repack into A (reuse registers)
#pragma unroll
            for (int kt = 0; kt < 4; kt++) {
#pragma unroll
                for (int half = 0; half < 2; half++) {
                    const int nt = 2 * kt + half;
                    const int col0 = nt * 8 + (lane & 3) * 2;
                    float2 bb = *(const float2*)(s_b1 + col0);
                    A[kt][2 * half + 0] =
                        pack_f16x2(fmaxf(C[nt][0] + bb.x, 0.0f),
                                   fmaxf(C[nt][1] + bb.y, 0.0f));
                    A[kt][2 * half + 1] =
                        pack_f16x2(fmaxf(C[nt][2] + bb.x, 0.0f),
                                   fmaxf(C[nt][3] + bb.y, 0.0f));
                }
            }
            float L[4] = {0.0f, 0.0f, 0.0f, 0.0f};
#pragma unroll
            for (int kg = 0; kg < 2; kg++) {
                mma16816(L, A[2 * kg], BF[kg]);
                mma16816(L, A[2 * kg + 1], BF[kg] + 2);
            }
            // lanes with (lane&3)==0 hold cols 0,1 = logits for rows
            // lane>>2 and lane>>2 + 8
            if ((lane & 3) == 0) {
                const int e0 = tile * 128 + warp * 32 + mt * 16 + (lane >> 2);
                float la0 = L[0] + s_bf[0], la1 = L[1] + s_bf[1];
                float m0 = fmaxf(la0, la1);
                float ea = __expf(la0 - m0), eb = __expf(la1 - m0);
                float inv = 1.0f / (ea + eb);
                if (e0 < nE)
                    *(float2*)(out + 2 * (size_t)e0) = make_float2(ea * inv, eb * inv);

                const int e1 = e0 + 8;
                float lb0 = L[2] + s_bf[0], lb1 = L[3] + s_bf[1];
                float m1 = fmaxf(lb0, lb1);
                float ec = __expf(lb0 - m1), ed = __expf(lb1 - m1);
                float inv2 = 1.0f / (ec + ed);
                if (e1 < nE)
                    *(float2*)(out + 2 * (size_t)e1) = make_float2(ec * inv2, ed * inv2);
            }
        }

        if (write_labels && valid)
            out[2 * (size_t)nE + e] = lab;

        r = rn; c = cn;
        __syncwarp();   // A-tile rows reused next iteration by this warp only
    }
}

// ---------------------------------------------------------------------------
extern "C" void kernel_launch(void* const* d_in, const int* in_sizes, int n_in,
                              void* d_out, int out_size)
{
    const float* pcd         = (const float*)d_in[0];
    const float* feats       = (const float*)d_in[1];
    const float* also_pts    = (const float*)d_in[2];
    const int*   also_labels = (const int*)d_in[3];
    const int*   row         = (const int*)d_in[4];
    const int*   col         = (const int*)d_in[5];
    const float* w_in        = (const float*)d_in[6];
    const float* b_in        = (const float*)d_in[7];
    const float* w1          = (const float*)d_in[8];
    const float* b1          = (const float*)d_in[9];
    const float* w2          = (const float*)d_in[10];
    const float* b2          = (const float*)d_in[11];
    const float* w_out       = (const float*)d_in[12];
    const float* b_out       = (const float*)d_in[13];

    int nPts = in_sizes[1] / 64;
    if (nPts > 100000) nPts = 100000;
    int nPcd = in_sizes[0] / 3;
    if (nPcd > 100000) nPcd = 100000;
    int nApts = in_sizes[2] / 3;
    if (nApts > 100000) nApts = 100000;
    int nE = in_sizes[4];
    int nTiles = (nE + 127) / 128;
    int write_labels = ((long long)out_size >= 3LL * nE) ? 1 : 0;

    static int attr_done = 0;
    if (!attr_done) {
        cudaFuncSetAttribute(edge_mma_kernel,
                             cudaFuncAttributeMaxDynamicSharedMemorySize, SM_TOTAL);
        attr_done = 1;
    }

    int gBlocks = (nPts + 127) / 128;
    int nmax = nPcd > nApts ? nPcd : nApts;
    int padBlocks = (nmax + 127) / 128;
    precompute_kernel<<<gBlocks + 16 + padBlocks, 128>>>(
        feats, w_in, b_in, nPts, w1, w2, b2, w_out, b_out,
        pcd, nPcd, also_pts, also_labels, nApts, gBlocks);

    int grid = 148 * 4;
    if (grid > nTiles) grid = nTiles;
    edge_mma_kernel<<<grid, 128, SM_TOTAL>>>(row, col, w_in, b1,
                                             (float*)d_out, nE, nTiles, write_labels);
}

// round 16
// speedup vs baseline: 1.5787x; 1.1984x over previous
#include <cuda_runtime.h>
#include <cuda_fp16.h>
#include <cstdint>

typedef unsigned long long ull;

// Precomputed g = feats @ w_in[0:64,:] + b_in  (N x 64), stored fp16
__device__ __half g_buf[100000 * 64];
// Packed fp16 weights: w1 only (64x64 fp16 = 2048 u32)
__device__ uint32_t w_pack[2048];
// Fused output weights: wf = w2 @ w_out (64x2 f32), bf = b2 @ w_out + b_out
__device__ float wf_buf[128];
__device__ float bf_buf[2];
// float4-padded points; apts4.w carries the label as float
__device__ float4 pcd4[100000];
__device__ float4 apts4[100000];

// ---------------------------------------------------------------------------
// helpers
// ---------------------------------------------------------------------------
__device__ __forceinline__ uint32_t smem_u32(const void* p) {
    uint32_t a;
    asm("{ .reg .u64 t; cvta.to.shared.u64 t, %1; cvt.u32.u64 %0, t; }" : "=r"(a) : "l"(p));
    return a;
}
__device__ __forceinline__ uint32_t pack_f16x2(float lo, float hi) {
    __half2 h = __floats2half2_rn(lo, hi);      // lo -> low half
    return *reinterpret_cast<uint32_t*>(&h);
}
__device__ __forceinline__ __half2 u2h2(uint32_t v) {
    return *reinterpret_cast<__half2*>(&v);
}
__device__ __forceinline__ uint32_t h2u2(__half2 v) {
    return *reinterpret_cast<uint32_t*>(&v);
}
__device__ __forceinline__ void ldsm_x4(uint32_t* r, uint32_t addr) {
    asm volatile("ldmatrix.sync.aligned.m8n8.x4.shared.b16 {%0,%1,%2,%3}, [%4];"
                 : "=r"(r[0]), "=r"(r[1]), "=r"(r[2]), "=r"(r[3]) : "r"(addr));
}
__device__ __forceinline__ void ldsm_x4_t(uint32_t* r, uint32_t addr) {
    asm volatile("ldmatrix.sync.aligned.m8n8.x4.trans.shared.b16 {%0,%1,%2,%3}, [%4];"
                 : "=r"(r[0]), "=r"(r[1]), "=r"(r[2]), "=r"(r[3]) : "r"(addr));
}
__device__ __forceinline__ void mma16816(float* c, const uint32_t* a, const uint32_t* b) {
    asm volatile(
        "mma.sync.aligned.m16n8k16.row.col.f32.f16.f16.f32 "
        "{%0,%1,%2,%3}, {%4,%5,%6,%7}, {%8,%9}, {%0,%1,%2,%3};"
        : "+f"(c[0]), "+f"(c[1]), "+f"(c[2]), "+f"(c[3])
        : "r"(a[0]), "r"(a[1]), "r"(a[2]), "r"(a[3]), "r"(b[0]), "r"(b[1]));
}

// ---------------------------------------------------------------------------
// Kernel 0 (small prologue):
//   blocks [0, 16):    fp16 conversion of w1; block 0 also builds wf/bf
//   blocks [16, end):  pad pcd/apts into float4 (label -> apts4.w)
// ---------------------------------------------------------------------------
__global__ void __launch_bounds__(128) small_prologue_kernel(
    const float* __restrict__ w1g, const float* __restrict__ w2g,
    const float* __restrict__ b2g, const float* __restrict__ w_outg,
    const float* __restrict__ b_outg,
    const float* __restrict__ pcd, int nPcd,
    const float* __restrict__ apts, const int* __restrict__ labels, int nApts)
{
    if (blockIdx.x >= 16u) {
        int i = (blockIdx.x - 16) * 128 + threadIdx.x;
        if (i < nPcd)
            pcd4[i] = make_float4(pcd[3 * i], pcd[3 * i + 1], pcd[3 * i + 2], 0.0f);
        if (i < nApts)
            apts4[i] = make_float4(apts[3 * i], apts[3 * i + 1], apts[3 * i + 2],
                                   (float)labels[i]);
        return;
    }
    int idx = blockIdx.x * 128 + threadIdx.x;  // 0..2047
    w_pack[idx] = pack_f16x2(w1g[2 * idx], w1g[2 * idx + 1]);
    if (blockIdx.x == 0) {
        int i = threadIdx.x >> 1;       // 0..63
        int o = threadIdx.x & 1;        // 0..1
        float s = 0.0f;
        for (int k = 0; k < 64; k++)
            s = fmaf(w2g[i * 64 + k], w_outg[k * 2 + o], s);
        wf_buf[i * 2 + o] = s;
        if (threadIdx.x < 2) {
            float sb = b_outg[threadIdx.x];
            for (int k = 0; k < 64; k++)
                sb = fmaf(b2g[k], w_outg[k * 2 + threadIdx.x], sb);
            bf_buf[threadIdx.x] = sb;
        }
    }
}

// ---------------------------------------------------------------------------
// Kernel 1: g = fp16(feats @ w_in[0:64,:] + b_in) via tensor cores.
// 128 points/block, 4 warps, 32 points/warp. Dense coalesced loads.
// SMEM: [0) w_in tile [64][72 fp16] 9216 | [9216) A tile [128][72] 18432
//       [27648) b_in 64 f32
// ---------------------------------------------------------------------------
#define GM_W     0
#define GM_A     9216
#define GM_B     27648
#define GM_TOTAL 27904

__global__ void __launch_bounds__(128) g_mma_kernel(
    const float* __restrict__ feats, const float* __restrict__ w_in,
    const float* __restrict__ b_in, int n_pts)
{
    __shared__ __align__(16) char smem[GM_TOTAL];
    const int tid = threadIdx.x;
    const int lane = tid & 31;
    const int warp = tid >> 5;

    // stage w_in rows 0..63 as fp16 (144B stride)
    for (int idx = tid; idx < 2048; idx += 128) {
        int rk = idx >> 5, cc = idx & 31;
        *(uint32_t*)(smem + GM_W + rk * 144 + cc * 4) =
            pack_f16x2(w_in[2 * idx], w_in[2 * idx + 1]);
    }
    float* s_b = (float*)(smem + GM_B);
    if (tid < 64) s_b[tid] = b_in[tid];

    const uint32_t sbase = smem_u32(smem);
    const uint32_t sA = sbase + GM_A;
    const int esub = lane >> 3;
    const int part = lane & 7;
    const int base = blockIdx.x * 128;

    // cooperative coalesced load of feats tile -> fp16 A smem
#pragma unroll
    for (int i = 0; i < 8; i++) {
        const int rloc = warp * 32 + 4 * i + esub;
        int grow = base + rloc;
        if (grow >= n_pts) grow = n_pts - 1;
        const float4* fp = (const float4*)(feats + (size_t)grow * 64 + part * 8);
        float4 v0 = fp[0], v1 = fp[1];
        uint32_t h0 = pack_f16x2(v0.x, v0.y);
        uint32_t h1 = pack_f16x2(v0.z, v0.w);
        uint32_t h2 = pack_f16x2(v1.x, v1.y);
        uint32_t h3 = pack_f16x2(v1.z, v1.w);
        asm volatile("st.shared.v4.b32 [%0], {%1,%2,%3,%4};" ::
                     "r"(sA + (uint32_t)rloc * 144 + part * 16),
                     "r"(h0), "r"(h1), "r"(h2), "r"(h3));
    }
    __syncthreads();

    const int a_row = (lane & 7) + ((lane >> 3) & 1) * 8;
    const int a_c8 = ((lane >> 4) & 1) * 8;
    const int b_row = (lane & 7) + ((lane >> 3) & 3) * 8;

    uint32_t A[2][4][4];
#pragma unroll
    for (int mt = 0; mt < 2; mt++) {
        const int rowm = warp * 32 + mt * 16 + a_row;
#pragma unroll
        for (int kt = 0; kt < 4; kt++)
            ldsm_x4(A[mt][kt], sA + (uint32_t)rowm * 144 + (kt * 16 + a_c8) * 2);
    }

    float C[2][8][4];
#pragma unroll
    for (int mt = 0; mt < 2; mt++)
#pragma unroll
        for (int nt = 0; nt < 8; nt++)
#pragma unroll
            for (int i = 0; i < 4; i++) C[mt][nt][i] = 0.0f;

#pragma unroll
    for (int kg = 0; kg < 2; kg++) {
#pragma unroll
        for (int nt = 0; nt < 8; nt++) {
            uint32_t B[4];
            ldsm_x4_t(B, sbase + GM_W + (uint32_t)(kg * 32 + b_row) * 144 + nt * 16);
#pragma unroll
            for (int mt = 0; mt < 2; mt++) {
                mma16816(C[mt][nt], A[mt][2 * kg], B);
                mma16816(C[mt][nt], A[mt][2 * kg + 1], B + 2);
            }
        }
    }

    // epilogue: g = C + b_in -> fp16, direct stores from fragment layout
#pragma unroll
    for (int mt = 0; mt < 2; mt++) {
        const int r0 = base + warp * 32 + mt * 16 + (lane >> 2);
        const int r1 = r0 + 8;
#pragma unroll
        for (int nt = 0; nt < 8; nt++) {
            const int col0 = nt * 8 + (lane & 3) * 2;
            float2 bb = *(const float2*)(s_b + col0);
            if (r0 < n_pts)
                *(uint32_t*)(g_buf + (size_t)r0 * 64 + col0) =
                    pack_f16x2(C[mt][nt][0] + bb.x, C[mt][nt][1] + bb.y);
            if (r1 < n_pts)
                *(uint32_t*)(g_buf + (size_t)r1 * 64 + col0) =
                    pack_f16x2(C[mt][nt][2] + bb.x, C[mt][nt][3] + bb.y);
        }
    }
}

// ---------------------------------------------------------------------------
// Kernel 2: persistent mma.sync edge MLP (unchanged from R15 best).
// SMEM (bytes):
//   [0)      w1 tile [64][72 fp16] (144B stride)                      9216
//   [9216)   A tile [128][72] fp16 (144B stride)                      18432
//   [27648)  w3 (3x64 f32)                                            768
//   [28416)  wf16 tile [64][8 fp16] (16B stride)                      1024
//   [29440)  b1 (64 f32)                                              256
//   [29696)  bf (2 f32)
// ---------------------------------------------------------------------------
#define SM_W     0
#define SM_A     9216
#define SM_W3    27648
#define SM_WF16  28416
#define SM_B1    29440
#define SM_BF    29696
#define SM_TOTAL 29952

__global__ void __launch_bounds__(128, 4) edge_mma_kernel(
    const int* __restrict__ row,
    const int* __restrict__ col,
    const float* __restrict__ w_in,
    const float* __restrict__ b1g,
    float* __restrict__ out,
    int nE, int nTiles, int write_labels)
{
    extern __shared__ __align__(16) char smem[];
    const int tid = threadIdx.x;
    const int lane = tid & 31;
    const int warp = tid >> 5;
    const uint32_t FULL = 0xFFFFFFFFu;

    // ---- stage weights into SMEM ----
    for (int idx = tid; idx < 2048; idx += 128) {
        int rk = idx >> 5, cc = idx & 31;
        *(uint32_t*)(smem + SM_W + rk * 144 + cc * 4) = w_pack[idx];
    }
    float* s_w3 = (float*)(smem + SM_W3);
    __half* s_wf16 = (__half*)(smem + SM_WF16);
    float* s_b1 = (float*)(smem + SM_B1);
    float* s_bf = (float*)(smem + SM_BF);
    for (int idx = tid; idx < 192; idx += 128) s_w3[idx] = w_in[64 * 64 + idx];
    // wf16: [64 k-rows][8 n-cols], cols 0,1 = wf, cols 2..7 = 0
    if (tid < 128) {
        int k = tid >> 1, o = tid & 1;
        s_wf16[k * 8 + o] = __float2half_rn(wf_buf[k * 2 + o]);
    }
    {
        int idx = tid;                 // 64 rows x 6 cols = 384 entries
        for (; idx < 384; idx += 128) {
            int k = idx / 6, o = 2 + idx % 6;
            s_wf16[k * 8 + o] = __float2half_rn(0.0f);
        }
    }
    if (tid < 64) s_b1[tid] = b1g[tid];
    if (tid < 2) s_bf[tid] = bf_buf[tid];
    __syncthreads();

    const uint32_t sbase = smem_u32(smem);
    const uint32_t sA = sbase + SM_A;

    const int a_row = (lane & 7) + ((lane >> 3) & 1) * 8;      // 0..15
    const int a_c8 = ((lane >> 4) & 1) * 8;                     // 0 / +8 cols
    const int b_row = (lane & 7) + ((lane >> 3) & 3) * 8;       // 0..31

    // hoisted wf B fragments (tile-invariant): 2 kg x 4 regs
    uint32_t BF[2][4];
#pragma unroll
    for (int kg = 0; kg < 2; kg++)
        ldsm_x4_t(BF[kg], sbase + SM_WF16 + (uint32_t)(kg * 32 + b_row) * 16);

    // per-lane cooperative-gather mapping + w3 column slice as half2 (constant)
    const int esub = lane >> 3;          // which of 4 edges this lane serves
    const int part = lane & 7;           // which 16B chunk of the row
    __half2 w3h[3][4];
#pragma unroll
    for (int rr = 0; rr < 3; rr++)
#pragma unroll
        for (int p = 0; p < 4; p++)
            w3h[rr][p] = __floats2half2_rn(s_w3[rr * 64 + part * 8 + 2 * p],
                                           s_w3[rr * 64 + part * 8 + 2 * p + 1]);
    const __half2 hzero = __floats2half2_rn(0.0f, 0.0f);

    // preload first tile's indices
    int r = 0, c = 0;
    if (blockIdx.x < nTiles) {
        int e0 = blockIdx.x * 128 + tid;
        int ee = e0 < nE ? e0 : nE - 1;
        r = row[ee]; c = col[ee];
    }

    for (int tile = blockIdx.x; tile < nTiles; tile += gridDim.x) {
        const int e = tile * 128 + tid;
        const bool valid = e < nE;

        // preload next tile's indices (registers only, coalesced)
        int rn = r, cn = c;
        {
            int tn = tile + gridDim.x;
            if (tn < nTiles) {
                int en = tn * 128 + tid;
                int een = en < nE ? en : nE - 1;
                rn = row[een]; cn = col[een];
            }
        }

        const float4 ap = apts4[r];
        const float4 pc = pcd4[c];
        const uint32_t h00 = pack_f16x2(ap.x - pc.x, ap.x - pc.x);
        const uint32_t h11 = pack_f16x2(ap.y - pc.y, ap.y - pc.y);
        const uint32_t h22 = pack_f16x2(ap.z - pc.z, ap.z - pc.z);
        const float lab = ap.w;

        // ---- stage A (cooperative, half2): 8 lanes per edge row ----
#pragma unroll
        for (int i = 0; i < 8; i++) {
            const int eg = 4 * i + esub;                       // edge-in-warp
            const int cg = __shfl_sync(FULL, c, eg);
            const __half2 q0 = u2h2(__shfl_sync(FULL, h00, eg));
            const __half2 q1 = u2h2(__shfl_sync(FULL, h11, eg));
            const __half2 q2 = u2h2(__shfl_sync(FULL, h22, eg));
            const uint4 v = *(const uint4*)(g_buf + (size_t)cg * 64 + part * 8);
            uint32_t w[4] = {v.x, v.y, v.z, v.w};
            uint32_t h4[4];
#pragma unroll
            for (int p = 0; p < 4; p++) {
                __half2 hv = u2h2(w[p]);
                hv = __hfma2(q0, w3h[0][p], hv);
                hv = __hfma2(q1, w3h[1][p], hv);
                hv = __hfma2(q2, w3h[2][p], hv);
                hv = __hmax2(hv, hzero);
                h4[p] = h2u2(hv);
            }
            asm volatile("st.shared.v4.b32 [%0], {%1,%2,%3,%4};" ::
                         "r"(sA + (uint32_t)(warp * 32 + eg) * 144 + part * 16),
                         "r"(h4[0]), "r"(h4[1]), "r"(h4[2]), "r"(h4[3]));
        }
        __syncwarp();

        // ==== process the two 16-edge m-tiles sequentially (reg pressure) ====
#pragma unroll 1
        for (int mt = 0; mt < 2; mt++) {
            // ---- load A fragments ----
            uint32_t A[4][4];
            {
                const int rowm = warp * 32 + mt * 16 + a_row;
#pragma unroll
                for (int kt = 0; kt < 4; kt++)
                    ldsm_x4(A[kt], sA + (uint32_t)rowm * 144 + (kt * 16 + a_c8) * 2);
            }

            // ---- hidden layer (w1) ----
            float C[8][4];
#pragma unroll
            for (int nt = 0; nt < 8; nt++)
#pragma unroll
                for (int i = 0; i < 4; i++) C[nt][i] = 0.0f;

#pragma unroll
            for (int kg = 0; kg < 2; kg++) {
#pragma unroll
                for (int nt = 0; nt < 8; nt++) {
                    uint32_t B[4];
                    ldsm_x4_t(B, sbase + SM_W + (uint32_t)(kg * 32 + b_row) * 144 + nt * 16);
                    mma16816(C[nt], A[2 * kg], B);
                    mma16816(C[nt], A[2 * kg + 1], B + 2);
                }
            }

            // ---- tensor-core epilogue: logits = relu(C + b1) @ wf16 + bf ----
#pragma unroll
            for (int kt = 0; kt < 4; kt++) {
#pragma unroll
                for (int half = 0; half < 2; half++) {
                    const int nt = 2 * kt + half;
                    const int col0 = nt * 8 + (lane & 3) * 2;
                    float2 bb = *(const float2*)(s_b1 + col0);
                    A[kt][2 * half + 0] =
                        pack_f16x2(fmaxf(C[nt][0] + bb.x, 0.0f),
                                   fmaxf(C[nt][1] + bb.y, 0.0f));
                    A[kt][2 * half + 1] =
                        pack_f16x2(fmaxf(C[nt][2] + bb.x, 0.0f),
                                   fmaxf(C[nt][3] + bb.y, 0.0f));
                }
            }
            float L[4] = {0.0f, 0.0f, 0.0f, 0.0f};
#pragma unroll
            for (int kg = 0; kg < 2; kg++) {
                mma16816(L, A[2 * kg], BF[kg]);
                mma16816(L, A[2 * kg + 1], BF[kg] + 2);
            }
            if ((lane & 3) == 0) {
                const int e0 = tile * 128 + warp * 32 + mt * 16 + (lane >> 2);
                float la0 = L[0] + s_bf[0], la1 = L[1] + s_bf[1];
                float m0 = fmaxf(la0, la1);
                float ea = __expf(la0 - m0), eb = __expf(la1 - m0);
                float inv = 1.0f / (ea + eb);
                if (e0 < nE)
                    *(float2*)(out + 2 * (size_t)e0) = make_float2(ea * inv, eb * inv);

                const int e1 = e0 + 8;
                float lb0 = L[2] + s_bf[0], lb1 = L[3] + s_bf[1];
                float m1 = fmaxf(lb0, lb1);
                float ec = __expf(lb0 - m1), ed = __expf(lb1 - m1);
                float inv2 = 1.0f / (ec + ed);
                if (e1 < nE)
                    *(float2*)(out + 2 * (size_t)e1) = make_float2(ec * inv2, ed * inv2);
            }
        }

        if (write_labels && valid)
            out[2 * (size_t)nE + e] = lab;

        r = rn; c = cn;
        __syncwarp();   // A-tile rows reused next iteration by this warp only
    }
}

// ---------------------------------------------------------------------------
extern "C" void kernel_launch(void* const* d_in, const int* in_sizes, int n_in,
                              void* d_out, int out_size)
{
    const float* pcd         = (const float*)d_in[0];
    const float* feats       = (const float*)d_in[1];
    const float* also_pts    = (const float*)d_in[2];
    const int*   also_labels = (const int*)d_in[3];
    const int*   row         = (const int*)d_in[4];
    const int*   col         = (const int*)d_in[5];
    const float* w_in        = (const float*)d_in[6];
    const float* b_in        = (const float*)d_in[7];
    const float* w1          = (const float*)d_in[8];
    const float* b1          = (const float*)d_in[9];
    const float* w2          = (const float*)d_in[10];
    const float* b2          = (const float*)d_in[11];
    const float* w_out       = (const float*)d_in[12];
    const float* b_out       = (const float*)d_in[13];

    int nPts = in_sizes[1] / 64;
    if (nPts > 100000) nPts = 100000;
    int nPcd = in_sizes[0] / 3;
    if (nPcd > 100000) nPcd = 100000;
    int nApts = in_sizes[2] / 3;
    if (nApts > 100000) nApts = 100000;
    int nE = in_sizes[4];
    int nTiles = (nE + 127) / 128;
    int write_labels = ((long long)out_size >= 3LL * nE) ? 1 : 0;

    static int attr_done = 0;
    if (!attr_done) {
        cudaFuncSetAttribute(edge_mma_kernel,
                             cudaFuncAttributeMaxDynamicSharedMemorySize, SM_TOTAL);
        attr_done = 1;
    }

    int nmax = nPcd > nApts ? nPcd : nApts;
    int padBlocks = (nmax + 127) / 128;
    small_prologue_kernel<<<16 + padBlocks, 128>>>(
        w1, w2, b2, w_out, b_out, pcd, nPcd, also_pts, also_labels, nApts);

    g_mma_kernel<<<(nPts + 127) / 128, 128>>>(feats, w_in, b_in, nPts);

    int grid = 148 * 4;
    if (grid > nTiles) grid = nTiles;
    edge_mma_kernel<<<grid, 128, SM_TOTAL>>>(row, col, w_in, b1,
                                             (float*)d_out, nE, nTiles, write_labels);
}

// round 17
// speedup vs baseline: 1.6357x; 1.0361x over previous
#include <cuda_runtime.h>
#include <cuda_fp16.h>
#include <cstdint>

typedef unsigned long long ull;

// Precomputed g = feats @ w_in[0:64,:] + b_in  (N x 64), stored fp16
__device__ __half g_buf[100000 * 64];
// Packed fp16 weights: w1 only (64x64 fp16 = 2048 u32)
__device__ uint32_t w_pack[2048];
// Fused output weights: wf = w2 @ w_out (64x2 f32), bf = b2 @ w_out + b_out
__device__ float wf_buf[128];
__device__ float bf_buf[2];
// float4-padded points; apts4.w carries the label as float
__device__ float4 pcd4[100000];
__device__ float4 apts4[100000];

// ---------------------------------------------------------------------------
// helpers
// ---------------------------------------------------------------------------
__device__ __forceinline__ uint32_t smem_u32(const void* p) {
    uint32_t a;
    asm("{ .reg .u64 t; cvta.to.shared.u64 t, %1; cvt.u32.u64 %0, t; }" : "=r"(a) : "l"(p));
    return a;
}
__device__ __forceinline__ uint32_t pack_f16x2(float lo, float hi) {
    __half2 h = __floats2half2_rn(lo, hi);      // lo -> low half
    return *reinterpret_cast<uint32_t*>(&h);
}
__device__ __forceinline__ __half2 u2h2(uint32_t v) {
    return *reinterpret_cast<__half2*>(&v);
}
__device__ __forceinline__ uint32_t h2u2(__half2 v) {
    return *reinterpret_cast<uint32_t*>(&v);
}
__device__ __forceinline__ void ldsm_x4(uint32_t* r, uint32_t addr) {
    asm volatile("ldmatrix.sync.aligned.m8n8.x4.shared.b16 {%0,%1,%2,%3}, [%4];"
                 : "=r"(r[0]), "=r"(r[1]), "=r"(r[2]), "=r"(r[3]) : "r"(addr));
}
__device__ __forceinline__ void ldsm_x4_t(uint32_t* r, uint32_t addr) {
    asm volatile("ldmatrix.sync.aligned.m8n8.x4.trans.shared.b16 {%0,%1,%2,%3}, [%4];"
                 : "=r"(r[0]), "=r"(r[1]), "=r"(r[2]), "=r"(r[3]) : "r"(addr));
}
__device__ __forceinline__ void mma16816(float* c, const uint32_t* a, const uint32_t* b) {
    asm volatile(
        "mma.sync.aligned.m16n8k16.row.col.f32.f16.f16.f32 "
        "{%0,%1,%2,%3}, {%4,%5,%6,%7}, {%8,%9}, {%0,%1,%2,%3};"
        : "+f"(c[0]), "+f"(c[1]), "+f"(c[2]), "+f"(c[3])
        : "r"(a[0]), "r"(a[1]), "r"(a[2]), "r"(a[3]), "r"(b[0]), "r"(b[1]));
}

// ---------------------------------------------------------------------------
// Kernel 1 (fused prologue, one launch):
//   blocks [0, gB):        g = fp16(feats @ w_in[0:64,:] + b_in) via mma
//   blocks [gB, gB+16):    fp16 conversion of w1; block gB builds wf/bf
//   blocks [gB+16, end):   pad pcd/apts into float4 (label -> apts4.w)
// dynamic smem = GM_TOTAL (used only by g blocks)
// ---------------------------------------------------------------------------
#define GM_W     0
#define GM_A     9216
#define GM_B     27648
#define GM_TOTAL 27904

__global__ void __launch_bounds__(128) prologue_kernel(
    const float* __restrict__ feats, const float* __restrict__ w_in,
    const float* __restrict__ b_in, int n_pts,
    const float* __restrict__ w1g, const float* __restrict__ w2g,
    const float* __restrict__ b2g, const float* __restrict__ w_outg,
    const float* __restrict__ b_outg,
    const float* __restrict__ pcd, int nPcd,
    const float* __restrict__ apts, const int* __restrict__ labels, int nApts,
    int gBlocks)
{
    const int tid = threadIdx.x;

    if (blockIdx.x >= (unsigned)(gBlocks + 16)) {
        int i = (blockIdx.x - gBlocks - 16) * 128 + tid;
        if (i < nPcd)
            pcd4[i] = make_float4(pcd[3 * i], pcd[3 * i + 1], pcd[3 * i + 2], 0.0f);
        if (i < nApts)
            apts4[i] = make_float4(apts[3 * i], apts[3 * i + 1], apts[3 * i + 2],
                                   (float)labels[i]);
        return;
    }
    if (blockIdx.x >= (unsigned)gBlocks) {
        int idx = (blockIdx.x - gBlocks) * 128 + tid;  // 0..2047
        w_pack[idx] = pack_f16x2(w1g[2 * idx], w1g[2 * idx + 1]);
        if (blockIdx.x == (unsigned)gBlocks) {
            int i = tid >> 1;           // 0..63
            int o = tid & 1;            // 0..1
            float s = 0.0f;
            for (int k = 0; k < 64; k++)
                s = fmaf(w2g[i * 64 + k], w_outg[k * 2 + o], s);
            wf_buf[i * 2 + o] = s;
            if (tid < 2) {
                float sb = b_outg[tid];
                for (int k = 0; k < 64; k++)
                    sb = fmaf(b2g[k], w_outg[k * 2 + tid], sb);
                bf_buf[tid] = sb;
            }
        }
        return;
    }

    // ---- g GEMM blocks ----
    extern __shared__ __align__(16) char smem[];
    const int lane = tid & 31;
    const int warp = tid >> 5;

    for (int idx = tid; idx < 2048; idx += 128) {
        int rk = idx >> 5, cc = idx & 31;
        *(uint32_t*)(smem + GM_W + rk * 144 + cc * 4) =
            pack_f16x2(w_in[2 * idx], w_in[2 * idx + 1]);
    }
    float* s_b = (float*)(smem + GM_B);
    if (tid < 64) s_b[tid] = b_in[tid];

    const uint32_t sbase = smem_u32(smem);
    const uint32_t sA = sbase + GM_A;
    const int esub = lane >> 3;
    const int part = lane & 7;
    const int base = blockIdx.x * 128;

#pragma unroll
    for (int i = 0; i < 8; i++) {
        const int rloc = warp * 32 + 4 * i + esub;
        int grow = base + rloc;
        if (grow >= n_pts) grow = n_pts - 1;
        const float4* fp = (const float4*)(feats + (size_t)grow * 64 + part * 8);
        float4 v0 = fp[0], v1 = fp[1];
        uint32_t h0 = pack_f16x2(v0.x, v0.y);
        uint32_t h1 = pack_f16x2(v0.z, v0.w);
        uint32_t h2 = pack_f16x2(v1.x, v1.y);
        uint32_t h3 = pack_f16x2(v1.z, v1.w);
        asm volatile("st.shared.v4.b32 [%0], {%1,%2,%3,%4};" ::
                     "r"(sA + (uint32_t)rloc * 144 + part * 16),
                     "r"(h0), "r"(h1), "r"(h2), "r"(h3));
    }
    __syncthreads();

    const int a_row = (lane & 7) + ((lane >> 3) & 1) * 8;
    const int a_c8 = ((lane >> 4) & 1) * 8;
    const int b_row = (lane & 7) + ((lane >> 3) & 3) * 8;

    uint32_t A[2][4][4];
#pragma unroll
    for (int mt = 0; mt < 2; mt++) {
        const int rowm = warp * 32 + mt * 16 + a_row;
#pragma unroll
        for (int kt = 0; kt < 4; kt++)
            ldsm_x4(A[mt][kt], sA + (uint32_t)rowm * 144 + (kt * 16 + a_c8) * 2);
    }

    float C[2][8][4];
#pragma unroll
    for (int mt = 0; mt < 2; mt++)
#pragma unroll
        for (int nt = 0; nt < 8; nt++)
#pragma unroll
            for (int i = 0; i < 4; i++) C[mt][nt][i] = 0.0f;

#pragma unroll
    for (int kg = 0; kg < 2; kg++) {
#pragma unroll
        for (int nt = 0; nt < 8; nt++) {
            uint32_t B[4];
            ldsm_x4_t(B, sbase + GM_W + (uint32_t)(kg * 32 + b_row) * 144 + nt * 16);
#pragma unroll
            for (int mt = 0; mt < 2; mt++) {
                mma16816(C[mt][nt], A[mt][2 * kg], B);
                mma16816(C[mt][nt], A[mt][2 * kg + 1], B + 2);
            }
        }
    }

#pragma unroll
    for (int mt = 0; mt < 2; mt++) {
        const int r0 = base + warp * 32 + mt * 16 + (lane >> 2);
        const int r1 = r0 + 8;
#pragma unroll
        for (int nt = 0; nt < 8; nt++) {
            const int col0 = nt * 8 + (lane & 3) * 2;
            float2 bb = *(const float2*)(s_b + col0);
            if (r0 < n_pts)
                *(uint32_t*)(g_buf + (size_t)r0 * 64 + col0) =
                    pack_f16x2(C[mt][nt][0] + bb.x, C[mt][nt][1] + bb.y);
            if (r1 < n_pts)
                *(uint32_t*)(g_buf + (size_t)r1 * 64 + col0) =
                    pack_f16x2(C[mt][nt][2] + bb.x, C[mt][nt][3] + bb.y);
        }
    }
}

// ---------------------------------------------------------------------------
// Kernel 2: persistent mma.sync edge MLP (unchanged from R15/R16 best).
// SMEM (bytes):
//   [0)      w1 tile [64][72 fp16] (144B stride)                      9216
//   [9216)   A tile [128][72] fp16 (144B stride)                      18432
//   [27648)  w3 (3x64 f32)                                            768
//   [28416)  wf16 tile [64][8 fp16] (16B stride)                      1024
//   [29440)  b1 (64 f32)                                              256
//   [29696)  bf (2 f32)
// ---------------------------------------------------------------------------
#define SM_W     0
#define SM_A     9216
#define SM_W3    27648
#define SM_WF16  28416
#define SM_B1    29440
#define SM_BF    29696
#define SM_TOTAL 29952

__global__ void __launch_bounds__(128, 4) edge_mma_kernel(
    const int* __restrict__ row,
    const int* __restrict__ col,
    const float* __restrict__ w_in,
    const float* __restrict__ b1g,
    float* __restrict__ out,
    int nE, int nTiles, int write_labels)
{
    extern __shared__ __align__(16) char smem[];
    const int tid = threadIdx.x;
    const int lane = tid & 31;
    const int warp = tid >> 5;
    const uint32_t FULL = 0xFFFFFFFFu;

    // ---- stage weights into SMEM ----
    for (int idx = tid; idx < 2048; idx += 128) {
        int rk = idx >> 5, cc = idx & 31;
        *(uint32_t*)(smem + SM_W + rk * 144 + cc * 4) = w_pack[idx];
    }
    float* s_w3 = (float*)(smem + SM_W3);
    __half* s_wf16 = (__half*)(smem + SM_WF16);
    float* s_b1 = (float*)(smem + SM_B1);
    float* s_bf = (float*)(smem + SM_BF);
    for (int idx = tid; idx < 192; idx += 128) s_w3[idx] = w_in[64 * 64 + idx];
    // wf16: [64 k-rows][8 n-cols], cols 0,1 = wf, cols 2..7 = 0
    if (tid < 128) {
        int k = tid >> 1, o = tid & 1;
        s_wf16[k * 8 + o] = __float2half_rn(wf_buf[k * 2 + o]);
    }
    {
        int idx = tid;                 // 64 rows x 6 cols = 384 entries
        for (; idx < 384; idx += 128) {
            int k = idx / 6, o = 2 + idx % 6;
            s_wf16[k * 8 + o] = __float2half_rn(0.0f);
        }
    }
    if (tid < 64) s_b1[tid] = b1g[tid];
    if (tid < 2) s_bf[tid] = bf_buf[tid];
    __syncthreads();

    const uint32_t sbase = smem_u32(smem);
    const uint32_t sA = sbase + SM_A;

    const int a_row = (lane & 7) + ((lane >> 3) & 1) * 8;      // 0..15
    const int a_c8 = ((lane >> 4) & 1) * 8;                     // 0 / +8 cols
    const int b_row = (lane & 7) + ((lane >> 3) & 3) * 8;       // 0..31

    // hoisted wf B fragments (tile-invariant): 2 kg x 4 regs
    uint32_t BF[2][4];
#pragma unroll
    for (int kg = 0; kg < 2; kg++)
        ldsm_x4_t(BF[kg], sbase + SM_WF16 + (uint32_t)(kg * 32 + b_row) * 16);

    // per-lane cooperative-gather mapping + w3 column slice as half2 (constant)
    const int esub = lane >> 3;          // which of 4 edges this lane serves
    const int part = lane & 7;           // which 16B chunk of the row
    __half2 w3h[3][4];
#pragma unroll
    for (int rr = 0; rr < 3; rr++)
#pragma unroll
        for (int p = 0; p < 4; p++)
            w3h[rr][p] = __floats2half2_rn(s_w3[rr * 64 + part * 8 + 2 * p],
                                           s_w3[rr * 64 + part * 8 + 2 * p + 1]);
    const __half2 hzero = __floats2half2_rn(0.0f, 0.0f);

    // preload first tile's indices
    int r = 0, c = 0;
    if (blockIdx.x < nTiles) {
        int e0 = blockIdx.x * 128 + tid;
        int ee = e0 < nE ? e0 : nE - 1;
        r = row[ee]; c = col[ee];
    }

    for (int tile = blockIdx.x; tile < nTiles; tile += gridDim.x) {
        const int e = tile * 128 + tid;
        const bool valid = e < nE;

        // preload next tile's indices (registers only, coalesced)
        int rn = r, cn = c;
        {
            int tn = tile + gridDim.x;
            if (tn < nTiles) {
                int en = tn * 128 + tid;
                int een = en < nE ? en : nE - 1;
                rn = row[een]; cn = col[een];
            }
        }

        const float4 ap = apts4[r];
        const float4 pc = pcd4[c];
        const uint32_t h00 = pack_f16x2(ap.x - pc.x, ap.x - pc.x);
        const uint32_t h11 = pack_f16x2(ap.y - pc.y, ap.y - pc.y);
        const uint32_t h22 = pack_f16x2(ap.z - pc.z, ap.z - pc.z);
        const float lab = ap.w;

        // ---- stage A (cooperative, half2): 8 lanes per edge row ----
#pragma unroll
        for (int i = 0; i < 8; i++) {
            const int eg = 4 * i + esub;                       // edge-in-warp
            const int cg = __shfl_sync(FULL, c, eg);
            const __half2 q0 = u2h2(__shfl_sync(FULL, h00, eg));
            const __half2 q1 = u2h2(__shfl_sync(FULL, h11, eg));
            const __half2 q2 = u2h2(__shfl_sync(FULL, h22, eg));
            const uint4 v = *(const uint4*)(g_buf + (size_t)cg * 64 + part * 8);
            uint32_t w[4] = {v.x, v.y, v.z, v.w};
            uint32_t h4[4];
#pragma unroll
            for (int p = 0; p < 4; p++) {
                __half2 hv = u2h2(w[p]);
                hv = __hfma2(q0, w3h[0][p], hv);
                hv = __hfma2(q1, w3h[1][p], hv);
                hv = __hfma2(q2, w3h[2][p], hv);
                hv = __hmax2(hv, hzero);
                h4[p] = h2u2(hv);
            }
            asm volatile("st.shared.v4.b32 [%0], {%1,%2,%3,%4};" ::
                         "r"(sA + (uint32_t)(warp * 32 + eg) * 144 + part * 16),
                         "r"(h4[0]), "r"(h4[1]), "r"(h4[2]), "r"(h4[3]));
        }
        __syncwarp();

        // ==== process the two 16-edge m-tiles sequentially (reg pressure) ====
#pragma unroll 1
        for (int mt = 0; mt < 2; mt++) {
            // ---- load A fragments ----
            uint32_t A[4][4];
            {
                const int rowm = warp * 32 + mt * 16 + a_row;
#pragma unroll
                for (int kt = 0; kt < 4; kt++)
                    ldsm_x4(A[kt], sA + (uint32_t)rowm * 144 + (kt * 16 + a_c8) * 2);
            }

            // ---- hidden layer (w1) ----
            float C[8][4];
#pragma unroll
            for (int nt = 0; nt < 8; nt++)
#pragma unroll
                for (int i = 0; i < 4; i++) C[nt][i] = 0.0f;

#pragma unroll
            for (int kg = 0; kg < 2; kg++) {
#pragma unroll
                for (int nt = 0; nt < 8; nt++) {
                    uint32_t B[4];
                    ldsm_x4_t(B, sbase + SM_W + (uint32_t)(kg * 32 + b_row) * 144 + nt * 16);
                    mma16816(C[nt], A[2 * kg], B);
                    mma16816(C[nt], A[2 * kg + 1], B + 2);
                }
            }

            // ---- tensor-core epilogue: logits = relu(C + b1) @ wf16 + bf ----
#pragma unroll
            for (int kt = 0; kt < 4; kt++) {
#pragma unroll
                for (int half = 0; half < 2; half++) {
                    const int nt = 2 * kt + half;
                    const int col0 = nt * 8 + (lane & 3) * 2;
                    float2 bb = *(const float2*)(s_b1 + col0);
                    A[kt][2 * half + 0] =
                        pack_f16x2(fmaxf(C[nt][0] + bb.x, 0.0f),
                                   fmaxf(C[nt][1] + bb.y, 0.0f));
                    A[kt][2 * half + 1] =
                        pack_f16x2(fmaxf(C[nt][2] + bb.x, 0.0f),
                                   fmaxf(C[nt][3] + bb.y, 0.0f));
                }
            }
            float L[4] = {0.0f, 0.0f, 0.0f, 0.0f};
#pragma unroll
            for (int kg = 0; kg < 2; kg++) {
                mma16816(L, A[2 * kg], BF[kg]);
                mma16816(L, A[2 * kg + 1], BF[kg] + 2);
            }
            if ((lane & 3) == 0) {
                const int e0 = tile * 128 + warp * 32 + mt * 16 + (lane >> 2);
                float la0 = L[0] + s_bf[0], la1 = L[1] + s_bf[1];
                float m0 = fmaxf(la0, la1);
                float ea = __expf(la0 - m0), eb = __expf(la1 - m0);
                float inv = 1.0f / (ea + eb);
                if (e0 < nE)
                    *(float2*)(out + 2 * (size_t)e0) = make_float2(ea * inv, eb * inv);

                const int e1 = e0 + 8;
                float lb0 = L[2] + s_bf[0], lb1 = L[3] + s_bf[1];
                float m1 = fmaxf(lb0, lb1);
                float ec = __expf(lb0 - m1), ed = __expf(lb1 - m1);
                float inv2 = 1.0f / (ec + ed);
                if (e1 < nE)
                    *(float2*)(out + 2 * (size_t)e1) = make_float2(ec * inv2, ed * inv2);
            }
        }

        if (write_labels && valid)
            out[2 * (size_t)nE + e] = lab;

        r = rn; c = cn;
        __syncwarp();   // A-tile rows reused next iteration by this warp only
    }
}

// ---------------------------------------------------------------------------
extern "C" void kernel_launch(void* const* d_in, const int* in_sizes, int n_in,
                              void* d_out, int out_size)
{
    const float* pcd         = (const float*)d_in[0];
    const float* feats       = (const float*)d_in[1];
    const float* also_pts    = (const float*)d_in[2];
    const int*   also_labels = (const int*)d_in[3];
    const int*   row         = (const int*)d_in[4];
    const int*   col         = (const int*)d_in[5];
    const float* w_in        = (const float*)d_in[6];
    const float* b_in        = (const float*)d_in[7];
    const float* w1          = (const float*)d_in[8];
    const float* b1          = (const float*)d_in[9];
    const float* w2          = (const float*)d_in[10];
    const float* b2          = (const float*)d_in[11];
    const float* w_out       = (const float*)d_in[12];
    const float* b_out       = (const float*)d_in[13];

    int nPts = in_sizes[1] / 64;
    if (nPts > 100000) nPts = 100000;
    int nPcd = in_sizes[0] / 3;
    if (nPcd > 100000) nPcd = 100000;
    int nApts = in_sizes[2] / 3;
    if (nApts > 100000) nApts = 100000;
    int nE = in_sizes[4];
    int nTiles = (nE + 127) / 128;
    int write_labels = ((long long)out_size >= 3LL * nE) ? 1 : 0;

    static int attr_done = 0;
    if (!attr_done) {
        cudaFuncSetAttribute(edge_mma_kernel,
                             cudaFuncAttributeMaxDynamicSharedMemorySize, SM_TOTAL);
        cudaFuncSetAttribute(prologue_kernel,
                             cudaFuncAttributeMaxDynamicSharedMemorySize, GM_TOTAL);
        attr_done = 1;
    }

    int gBlocks = (nPts + 127) / 128;
    int nmax = nPcd > nApts ? nPcd : nApts;
    int padBlocks = (nmax + 127) / 128;
    prologue_kernel<<<gBlocks + 16 + padBlocks, 128, GM_TOTAL>>>(
        feats, w_in, b_in, nPts, w1, w2, b2, w_out, b_out,
        pcd, nPcd, also_pts, also_labels, nApts, gBlocks);

    int grid = 148 * 4;
    if (grid > nTiles) grid = nTiles;
    edge_mma_kernel<<<grid, 128, SM_TOTAL>>>(row, col, w_in, b1,
                                             (float*)d_out, nE, nTiles, write_labels);
}